// round 1
// baseline (speedup 1.0000x reference)
#include <cuda_runtime.h>
#include <cstdint>
#include <cstddef>

typedef unsigned long long u64;
typedef unsigned int u32;

#define N_PTS   65536
#define D_MODEL 256
#define FF_DIM  2048
#define WS      128
#define NH      8
#define DH      32
#define NLAYER  4

// ---------------- scratch (static device globals; no runtime allocation) ----
__device__ u64 g_keysA[N_PTS];
__device__ u64 g_keysB[N_PTS];
__device__ u32 g_hist[256 * 256];
__device__ float g_x  [(size_t)N_PTS * D_MODEL];     // 64 MB  hidden state
__device__ float g_qkv[(size_t)N_PTS * 3 * D_MODEL]; // 192 MB
__device__ float g_att[(size_t)N_PTS * D_MODEL];     // 64 MB
__device__ float g_tmp[(size_t)N_PTS * D_MODEL];     // 64 MB
__device__ float g_ff [(size_t)N_PTS * FF_DIM];      // 512 MB

// ---------------- morton keys -----------------------------------------------
// composite = (batch<<21 | morton21) << 16 | original_index  (40 bits, distinct)
__global__ void build_keys_kernel(const int* __restrict__ coords, u64* __restrict__ keys) {
    int i = blockIdx.x * 256 + threadIdx.x;
    int b = coords[i * 4 + 0];
    int x = coords[i * 4 + 1];
    int y = coords[i * 4 + 2];
    int z = coords[i * 4 + 3];
    u32 m = 0;
#pragma unroll
    for (int k = 0; k < 7; k++) {
        m |= ((u32)((x >> k) & 1) << (3 * k + 2))
           | ((u32)((y >> k) & 1) << (3 * k + 1))
           | ((u32)((z >> k) & 1) << (3 * k));
    }
    u64 key = ((u64)b << 21) | (u64)m;
    keys[i] = (key << 16) | (u32)i;
}

// ---------------- stable LSD radix sort (3 passes over bits 16..39) ---------
__global__ void radix_hist_kernel(const u64* __restrict__ in, int shift) {
    __shared__ u32 h[256];
    int t = threadIdx.x, b = blockIdx.x;
    h[t] = 0;
    __syncthreads();
    u32 d = (u32)((in[b * 256 + t] >> shift) & 0xFF);
    atomicAdd(&h[d], 1u);
    __syncthreads();
    g_hist[t * 256 + b] = h[t];   // digit-major layout
}

__global__ void radix_scan_kernel() {
    __shared__ u32 dt[256];
    __shared__ u32 ex[256];
    int d = threadIdx.x;
    u32 s = 0;
    for (int b = 0; b < 256; b++) s += g_hist[d * 256 + b];
    dt[d] = s;
    __syncthreads();
    if (d == 0) {
        u32 run = 0;
        for (int i = 0; i < 256; i++) { ex[i] = run; run += dt[i]; }
    }
    __syncthreads();
    u32 run = ex[d];
    for (int b = 0; b < 256; b++) {
        u32 t = g_hist[d * 256 + b];
        g_hist[d * 256 + b] = run;
        run += t;
    }
}

__global__ void radix_scatter_kernel(const u64* __restrict__ in, u64* __restrict__ out, int shift) {
    __shared__ unsigned char digs[256];
    int t = threadIdx.x, b = blockIdx.x;
    u64 key = in[b * 256 + t];
    u32 d = (u32)((key >> shift) & 0xFF);
    digs[t] = (unsigned char)d;
    __syncthreads();
    int rank = 0;
    for (int j = 0; j < t; j++) rank += (digs[j] == (unsigned char)d);
    out[g_hist[d * 256 + b] + rank] = key;
}

// ---------------- gather + positional embedding -----------------------------
__global__ void gather_pe_kernel(const u64* __restrict__ keys,
                                 const int* __restrict__ coords,
                                 const float* __restrict__ feat,
                                 const float* __restrict__ pex,
                                 const float* __restrict__ pey,
                                 const float* __restrict__ pez,
                                 const float* __restrict__ pes,
                                 float* __restrict__ x) {
    int i = blockIdx.x;        // sorted position
    int t = threadIdx.x;       // 0..255 (feature dim)
    int j = (int)(keys[i] & 0xFFFFu);
    int cx = coords[j * 4 + 1];
    int cy = coords[j * 4 + 2];
    int cz = coords[j * 4 + 3];
    x[(size_t)i * 256 + t] = feat[(size_t)j * 256 + t]
                           + pex[cx * 256 + t] + pey[cy * 256 + t]
                           + pez[cz * 256 + t] + pes[256 + t];  // pe_s[1]
}

// ---------------- fp32 tiled GEMM: C[M,N] = A[M,K] * B[N,K]^T + bias --------
#define BM 128
#define BN 64
#define BK 16
__global__ __launch_bounds__(256) void gemm_nt_kernel(
    const float* __restrict__ A, const float* __restrict__ B,
    const float* __restrict__ bias, float* __restrict__ C,
    int M, int Nn, int K, int relu)
{
    __shared__ float As[BK * BM];
    __shared__ float Bs[BK * BN];
    int tid = threadIdx.x;
    int tx = tid & 15, ty = tid >> 4;
    int m0 = blockIdx.y * BM;
    int n0 = blockIdx.x * BN;

    float acc[8][4];
#pragma unroll
    for (int i = 0; i < 8; i++)
#pragma unroll
        for (int j = 0; j < 4; j++) acc[i][j] = 0.f;

    const float* Ab = A + (size_t)m0 * K;
    const float* Bb = B + (size_t)n0 * K;

    for (int k0 = 0; k0 < K; k0 += BK) {
#pragma unroll
        for (int i = 0; i < 2; i++) {           // A tile: 128x16, 512 float4
            int q = tid + i * 256;
            int row = q >> 2, c4 = q & 3;
            float4 v = *(const float4*)(Ab + (size_t)row * K + k0 + c4 * 4);
            As[(c4 * 4 + 0) * BM + row] = v.x;
            As[(c4 * 4 + 1) * BM + row] = v.y;
            As[(c4 * 4 + 2) * BM + row] = v.z;
            As[(c4 * 4 + 3) * BM + row] = v.w;
        }
        {                                       // B tile: 64x16, 256 float4
            int row = tid >> 2, c4 = tid & 3;
            float4 v = *(const float4*)(Bb + (size_t)row * K + k0 + c4 * 4);
            Bs[(c4 * 4 + 0) * BN + row] = v.x;
            Bs[(c4 * 4 + 1) * BN + row] = v.y;
            Bs[(c4 * 4 + 2) * BN + row] = v.z;
            Bs[(c4 * 4 + 3) * BN + row] = v.w;
        }
        __syncthreads();
#pragma unroll
        for (int kk = 0; kk < BK; kk++) {
            float a[8], bb[4];
#pragma unroll
            for (int i = 0; i < 8; i++) a[i] = As[kk * BM + ty * 8 + i];
#pragma unroll
            for (int j = 0; j < 4; j++) bb[j] = Bs[kk * BN + tx * 4 + j];
#pragma unroll
            for (int i = 0; i < 8; i++)
#pragma unroll
                for (int j = 0; j < 4; j++) acc[i][j] += a[i] * bb[j];
        }
        __syncthreads();
    }

    float4 bv = *(const float4*)(bias + n0 + tx * 4);
    float bArr[4] = {bv.x, bv.y, bv.z, bv.w};
#pragma unroll
    for (int i = 0; i < 8; i++) {
        int m = m0 + ty * 8 + i;
        float4 o;
        o.x = acc[i][0] + bArr[0];
        o.y = acc[i][1] + bArr[1];
        o.z = acc[i][2] + bArr[2];
        o.w = acc[i][3] + bArr[3];
        if (relu) {
            o.x = fmaxf(o.x, 0.f); o.y = fmaxf(o.y, 0.f);
            o.z = fmaxf(o.z, 0.f); o.w = fmaxf(o.w, 0.f);
        }
        *(float4*)(C + (size_t)m * Nn + n0 + tx * 4) = o;
    }
}

// ---------------- windowed attention (online softmax) -----------------------
// one block per (window, head); 128 threads = one query row each
__global__ __launch_bounds__(128) void attn_kernel(const float* __restrict__ qkv,
                                                   float* __restrict__ att) {
    int w = blockIdx.x;
    int h = blockIdx.y;
    int p = threadIdx.x;
    __shared__ float Ks[WS][DH];
    __shared__ float Vs[WS][DH];

    const float* base = qkv + (size_t)w * WS * 768;
    const float* rowp = base + (size_t)p * 768;

#pragma unroll
    for (int d = 0; d < DH; d += 4) {
        *(float4*)&Ks[p][d] = *(const float4*)&rowp[256 + h * 32 + d];
        *(float4*)&Vs[p][d] = *(const float4*)&rowp[512 + h * 32 + d];
    }
    float q[DH];
#pragma unroll
    for (int d = 0; d < DH; d += 4) {
        float4 v = *(const float4*)&rowp[h * 32 + d];
        q[d] = v.x; q[d + 1] = v.y; q[d + 2] = v.z; q[d + 3] = v.w;
    }
    __syncthreads();

    const float scale = 0.17677669529663687f;  // 1/sqrt(32)
    float m = -1e30f, l = 0.f;
    float acc[DH];
#pragma unroll
    for (int d = 0; d < DH; d++) acc[d] = 0.f;

    for (int j = 0; j < WS; j++) {
        float s = 0.f;
#pragma unroll
        for (int d = 0; d < DH; d++) s += q[d] * Ks[j][d];
        s *= scale;
        float mn = fmaxf(m, s);
        float corr = __expf(m - mn);
        float e = __expf(s - mn);
        l = l * corr + e;
#pragma unroll
        for (int d = 0; d < DH; d++) acc[d] = acc[d] * corr + e * Vs[j][d];
        m = mn;
    }
    float inv = 1.f / l;
    float* out = att + ((size_t)w * WS + p) * 256 + h * 32;
#pragma unroll
    for (int d = 0; d < DH; d += 4) {
        float4 o;
        o.x = acc[d] * inv; o.y = acc[d + 1] * inv;
        o.z = acc[d + 2] * inv; o.w = acc[d + 3] * inv;
        *(float4*)&out[d] = o;
    }
}

// ---------------- fused residual add + LayerNorm ----------------------------
__global__ void add_ln_kernel(const float* __restrict__ resid,
                              const float* __restrict__ delta,
                              const float* __restrict__ gamma,
                              const float* __restrict__ beta,
                              float* __restrict__ out) {
    int row = blockIdx.x;
    int t = threadIdx.x;  // 256
    size_t idx = (size_t)row * 256 + t;
    float v = resid[idx] + delta[idx];

    __shared__ float red[8];
    float s = v;
#pragma unroll
    for (int o = 16; o > 0; o >>= 1) s += __shfl_xor_sync(0xffffffffu, s, o);
    if ((t & 31) == 0) red[t >> 5] = s;
    __syncthreads();
    if (t < 32) {
        float xr = (t < 8) ? red[t] : 0.f;
#pragma unroll
        for (int o = 4; o > 0; o >>= 1) xr += __shfl_xor_sync(0xffffffffu, xr, o);
        if (t == 0) red[0] = xr;
    }
    __syncthreads();
    float mean = red[0] * (1.f / 256.f);
    __syncthreads();

    float d = v - mean;
    float s2 = d * d;
#pragma unroll
    for (int o = 16; o > 0; o >>= 1) s2 += __shfl_xor_sync(0xffffffffu, s2, o);
    if ((t & 31) == 0) red[t >> 5] = s2;
    __syncthreads();
    if (t < 32) {
        float xr = (t < 8) ? red[t] : 0.f;
#pragma unroll
        for (int o = 4; o > 0; o >>= 1) xr += __shfl_xor_sync(0xffffffffu, xr, o);
        if (t == 0) red[0] = xr;
    }
    __syncthreads();
    float var = red[0] * (1.f / 256.f);
    out[idx] = d * rsqrtf(var + 1e-5f) * gamma[t] + beta[t];
}

// ---------------- launch ----------------------------------------------------
extern "C" void kernel_launch(void* const* d_in, const int* in_sizes, int n_in,
                              void* d_out, int out_size) {
    const int*   coords = (const int*)d_in[0];
    const float* feat   = (const float*)d_in[1];
    const float* pex    = (const float*)d_in[2];
    const float* pey    = (const float*)d_in[3];
    const float* pez    = (const float*)d_in[4];
    const float* pes    = (const float*)d_in[5];
    const float* Wqkv   = (const float*)d_in[6];
    const float* bqkv   = (const float*)d_in[7];
    const float* Wo     = (const float*)d_in[8];
    const float* bo     = (const float*)d_in[9];
    const float* W1     = (const float*)d_in[10];
    const float* b1     = (const float*)d_in[11];
    const float* W2     = (const float*)d_in[12];
    const float* b2     = (const float*)d_in[13];
    const float* g1     = (const float*)d_in[14];
    const float* be1    = (const float*)d_in[15];
    const float* g2     = (const float*)d_in[16];
    const float* be2    = (const float*)d_in[17];

    u64 *ka, *kb;
    float *xp, *qkvp, *attp, *tmpp, *ffp;
    cudaGetSymbolAddress((void**)&ka,   g_keysA);
    cudaGetSymbolAddress((void**)&kb,   g_keysB);
    cudaGetSymbolAddress((void**)&xp,   g_x);
    cudaGetSymbolAddress((void**)&qkvp, g_qkv);
    cudaGetSymbolAddress((void**)&attp, g_att);
    cudaGetSymbolAddress((void**)&tmpp, g_tmp);
    cudaGetSymbolAddress((void**)&ffp,  g_ff);

    // 1) morton keys + stable radix sort (3 passes over bits 16..39)
    build_keys_kernel<<<256, 256>>>(coords, ka);
    int shifts[3] = {16, 24, 32};
    u64* src = ka;
    u64* dst = kb;
    for (int p = 0; p < 3; p++) {
        radix_hist_kernel<<<256, 256>>>(src, shifts[p]);
        radix_scan_kernel<<<1, 256>>>();
        radix_scatter_kernel<<<256, 256>>>(src, dst, shifts[p]);
        u64* t = src; src = dst; dst = t;
    }
    // after 3 passes (odd count) sorted keys are in kb -> src now points to kb

    // 2) gather + positional embedding
    gather_pe_kernel<<<N_PTS, 256>>>(src, coords, feat, pex, pey, pez, pes, xp);

    // 3) transformer layers
    for (int l = 0; l < NLAYER; l++) {
        const float* wqkv = Wqkv + (size_t)l * 768 * 256;
        const float* bq   = bqkv + (size_t)l * 768;
        const float* wo   = Wo   + (size_t)l * 256 * 256;
        const float* bo_l = bo   + (size_t)l * 256;
        const float* w1   = W1   + (size_t)l * 2048 * 256;
        const float* b1_l = b1   + (size_t)l * 2048;
        const float* w2   = W2   + (size_t)l * 256 * 2048;
        const float* b2_l = b2   + (size_t)l * 256;

        gemm_nt_kernel<<<dim3(768 / BN, N_PTS / BM), 256>>>(
            xp, wqkv, bq, qkvp, N_PTS, 768, 256, 0);

        attn_kernel<<<dim3(N_PTS / WS, NH), WS>>>(qkvp, attp);

        gemm_nt_kernel<<<dim3(256 / BN, N_PTS / BM), 256>>>(
            attp, wo, bo_l, tmpp, N_PTS, 256, 256, 0);

        add_ln_kernel<<<N_PTS, 256>>>(xp, tmpp, g1 + l * 256, be1 + l * 256, xp);

        gemm_nt_kernel<<<dim3(2048 / BN, N_PTS / BM), 256>>>(
            xp, w1, b1_l, ffp, N_PTS, 2048, 256, 1);

        gemm_nt_kernel<<<dim3(256 / BN, N_PTS / BM), 256>>>(
            ffp, w2, b2_l, tmpp, N_PTS, 256, 2048, 0);

        add_ln_kernel<<<N_PTS, 256>>>(xp, tmpp, g2 + l * 256, be2 + l * 256, xp);
    }

    // 4) output
    cudaMemcpyAsync(d_out, xp, (size_t)N_PTS * D_MODEL * sizeof(float),
                    cudaMemcpyDeviceToDevice);
}

// round 2
// speedup vs baseline: 2.8100x; 2.8100x over previous
#include <cuda_runtime.h>
#include <cstdint>
#include <cstddef>

typedef unsigned long long u64;
typedef unsigned int u32;

#define N_PTS   65536
#define D_MODEL 256
#define FF_DIM  2048
#define WS      128
#define NH      8
#define DH      32
#define NLAYER  4

// ---------------- scratch (static device globals; no runtime allocation) ----
__device__ u64 g_keysA[N_PTS];
__device__ u64 g_keysB[N_PTS];
__device__ u32 g_hist[256 * 256];
__device__ float g_x  [(size_t)N_PTS * D_MODEL];
__device__ float g_qkv[(size_t)N_PTS * 3 * D_MODEL];
__device__ float g_att[(size_t)N_PTS * D_MODEL];
__device__ float g_tmp[(size_t)N_PTS * D_MODEL];
__device__ float g_ff [(size_t)N_PTS * FF_DIM];

// ---------------- morton keys ------------------------------------------------
__global__ void build_keys_kernel(const int* __restrict__ coords, u64* __restrict__ keys) {
    int i = blockIdx.x * 256 + threadIdx.x;
    int b = coords[i * 4 + 0];
    int x = coords[i * 4 + 1];
    int y = coords[i * 4 + 2];
    int z = coords[i * 4 + 3];
    u32 m = 0;
#pragma unroll
    for (int k = 0; k < 7; k++) {
        m |= ((u32)((x >> k) & 1) << (3 * k + 2))
           | ((u32)((y >> k) & 1) << (3 * k + 1))
           | ((u32)((z >> k) & 1) << (3 * k));
    }
    u64 key = ((u64)b << 21) | (u64)m;
    keys[i] = (key << 16) | (u32)i;
}

// ---------------- stable LSD radix sort (3 passes over bits 16..39) ----------
__global__ void radix_hist_kernel(const u64* __restrict__ in, int shift) {
    __shared__ u32 h[256];
    int t = threadIdx.x, b = blockIdx.x;
    h[t] = 0;
    __syncthreads();
    u32 d = (u32)((in[b * 256 + t] >> shift) & 0xFF);
    atomicAdd(&h[d], 1u);
    __syncthreads();
    g_hist[t * 256 + b] = h[t];
}

__global__ void radix_scan_kernel() {
    __shared__ u32 dt[256];
    __shared__ u32 ex[256];
    int d = threadIdx.x;
    u32 s = 0;
    for (int b = 0; b < 256; b++) s += g_hist[d * 256 + b];
    dt[d] = s;
    __syncthreads();
    if (d == 0) {
        u32 run = 0;
        for (int i = 0; i < 256; i++) { ex[i] = run; run += dt[i]; }
    }
    __syncthreads();
    u32 run = ex[d];
    for (int b = 0; b < 256; b++) {
        u32 t = g_hist[d * 256 + b];
        g_hist[d * 256 + b] = run;
        run += t;
    }
}

__global__ void radix_scatter_kernel(const u64* __restrict__ in, u64* __restrict__ out, int shift) {
    __shared__ unsigned char digs[256];
    int t = threadIdx.x, b = blockIdx.x;
    u64 key = in[b * 256 + t];
    u32 d = (u32)((key >> shift) & 0xFF);
    digs[t] = (unsigned char)d;
    __syncthreads();
    int rank = 0;
    for (int j = 0; j < t; j++) rank += (digs[j] == (unsigned char)d);
    out[g_hist[d * 256 + b] + rank] = key;
}

// ---------------- gather + positional embedding ------------------------------
__global__ void gather_pe_kernel(const u64* __restrict__ keys,
                                 const int* __restrict__ coords,
                                 const float* __restrict__ feat,
                                 const float* __restrict__ pex,
                                 const float* __restrict__ pey,
                                 const float* __restrict__ pez,
                                 const float* __restrict__ pes,
                                 float* __restrict__ x) {
    int i = blockIdx.x;
    int t = threadIdx.x;
    int j = (int)(keys[i] & 0xFFFFu);
    int cx = coords[j * 4 + 1];
    int cy = coords[j * 4 + 2];
    int cz = coords[j * 4 + 3];
    x[(size_t)i * 256 + t] = feat[(size_t)j * 256 + t]
                           + pex[cx * 256 + t] + pey[cy * 256 + t]
                           + pez[cz * 256 + t] + pes[256 + t];
}

// ---------------- tf32 mma.sync GEMM: C[M,N] = A[M,K]*B[N,K]^T + bias --------
#define GBM 128
#define GBN 128
#define GBK 32
#define NSTAGE 3
#define STAGE_ELEMS (GBM * GBK)

__device__ __forceinline__ void cp_async16(void* smem_dst, const void* gsrc) {
    u32 s = (u32)__cvta_generic_to_shared(smem_dst);
    asm volatile("cp.async.cg.shared.global [%0], [%1], 16;\n" :: "r"(s), "l"(gsrc));
}
__device__ __forceinline__ u32 f2tf32(float f) {
    u32 r;
    asm volatile("cvt.rna.tf32.f32 %0, %1;" : "=r"(r) : "f"(f));
    return r;
}

__global__ __launch_bounds__(256) void gemm_tf32_kernel(
    const float* __restrict__ A, const float* __restrict__ B,
    const float* __restrict__ bias, float* __restrict__ C,
    int M, int Nn, int K, int relu)
{
    extern __shared__ float smem[];
    float* As = smem;                                  // NSTAGE * 128*32
    float* Bs = smem + NSTAGE * STAGE_ELEMS;

    int tid  = threadIdx.x;
    int lane = tid & 31;
    int warp = tid >> 5;
    int wm = warp & 1;          // 2 warp rows (64 rows each)
    int wn = warp >> 1;         // 4 warp cols (32 cols each)
    int m0 = blockIdx.y * GBM;
    int n0 = blockIdx.x * GBN;

    const float* Ag = A + (size_t)m0 * K;
    const float* Bg = B + (size_t)n0 * K;

    float c[4][4][4];
#pragma unroll
    for (int i = 0; i < 4; i++)
#pragma unroll
        for (int j = 0; j < 4; j++)
#pragma unroll
            for (int k = 0; k < 4; k++) c[i][j][k] = 0.f;

    const int KT = K / GBK;

    // load one K-tile (stage) with cp.async; always commit a group
    auto load_stage = [&](int tile) {
        if (tile < KT) {
            int k0 = tile * GBK;
            float* Ad = As + (tile % NSTAGE) * STAGE_ELEMS;
            float* Bd = Bs + (tile % NSTAGE) * STAGE_ELEMS;
#pragma unroll
            for (int i = 0; i < 4; i++) {
                int q   = tid + i * 256;
                int row = q >> 3;
                int c4  = q & 7;
                int soff = (row * 8 + (c4 ^ (row & 7))) * 4;
                cp_async16(Ad + soff, Ag + (size_t)row * K + k0 + c4 * 4);
                cp_async16(Bd + soff, Bg + (size_t)row * K + k0 + c4 * 4);
            }
        }
        asm volatile("cp.async.commit_group;");
    };

    load_stage(0);
    load_stage(1);

    for (int kt = 0; kt < KT; kt++) {
        asm volatile("cp.async.wait_group 1;");
        __syncthreads();
        load_stage(kt + 2);

        const float* Ad = As + (kt % NSTAGE) * STAGE_ELEMS;
        const float* Bd = Bs + (kt % NSTAGE) * STAGE_ELEMS;

#pragma unroll
        for (int ks = 0; ks < 4; ks++) {
            int kk  = ks * 8 + (lane & 3);
            int kk2 = kk + 4;
            int kc  = kk >> 2;   // chunk index of kk  (= ks*2)
            int kc2 = kk2 >> 2;  // chunk index of kk2 (= ks*2+1)
            int r7  = lane >> 2; // row-within-8 for all fragment rows

            u32 af[4][4];
#pragma unroll
            for (int mt = 0; mt < 4; mt++) {
                int r  = wm * 64 + mt * 16 + (lane >> 2);
                int r2 = r + 8;
                af[mt][0] = f2tf32(Ad[(r  * 8 + (kc  ^ r7)) * 4 + (kk  & 3)]);
                af[mt][1] = f2tf32(Ad[(r2 * 8 + (kc  ^ r7)) * 4 + (kk  & 3)]);
                af[mt][2] = f2tf32(Ad[(r  * 8 + (kc2 ^ r7)) * 4 + (kk2 & 3)]);
                af[mt][3] = f2tf32(Ad[(r2 * 8 + (kc2 ^ r7)) * 4 + (kk2 & 3)]);
            }
            u32 bf[4][2];
#pragma unroll
            for (int nt = 0; nt < 4; nt++) {
                int n = wn * 32 + nt * 8 + (lane >> 2);
                bf[nt][0] = f2tf32(Bd[(n * 8 + (kc  ^ r7)) * 4 + (kk  & 3)]);
                bf[nt][1] = f2tf32(Bd[(n * 8 + (kc2 ^ r7)) * 4 + (kk2 & 3)]);
            }
#pragma unroll
            for (int mt = 0; mt < 4; mt++)
#pragma unroll
                for (int nt = 0; nt < 4; nt++) {
                    asm volatile(
                        "mma.sync.aligned.m16n8k8.row.col.f32.tf32.tf32.f32 "
                        "{%0,%1,%2,%3}, {%4,%5,%6,%7}, {%8,%9}, {%0,%1,%2,%3};"
                        : "+f"(c[mt][nt][0]), "+f"(c[mt][nt][1]),
                          "+f"(c[mt][nt][2]), "+f"(c[mt][nt][3])
                        : "r"(af[mt][0]), "r"(af[mt][1]), "r"(af[mt][2]), "r"(af[mt][3]),
                          "r"(bf[nt][0]), "r"(bf[nt][1]));
                }
        }
        __syncthreads();
    }

    // epilogue: bias (+relu), fp32 stores
#pragma unroll
    for (int mt = 0; mt < 4; mt++) {
#pragma unroll
        for (int nt = 0; nt < 4; nt++) {
            int row = m0 + wm * 64 + mt * 16 + (lane >> 2);
            int col = n0 + wn * 32 + nt * 8 + (lane & 3) * 2;
            float2 bv = *(const float2*)(bias + col);
            float v0 = c[mt][nt][0] + bv.x;
            float v1 = c[mt][nt][1] + bv.y;
            float v2 = c[mt][nt][2] + bv.x;
            float v3 = c[mt][nt][3] + bv.y;
            if (relu) {
                v0 = fmaxf(v0, 0.f); v1 = fmaxf(v1, 0.f);
                v2 = fmaxf(v2, 0.f); v3 = fmaxf(v3, 0.f);
            }
            float2 o0 = {v0, v1};
            float2 o1 = {v2, v3};
            *(float2*)(C + (size_t)row * Nn + col) = o0;
            *(float2*)(C + (size_t)(row + 8) * Nn + col) = o1;
        }
    }
}

// ---------------- windowed attention: two-pass softmax, smem scores ----------
// block = (window, head), 128 threads = one query row each
// smem: Ks[128][32] + Vs[128][32] + Sc[128][129]
#define ATTN_SMEM ((4096 + 4096 + 128 * 129) * 4)
__global__ __launch_bounds__(128) void attn2_kernel(const float* __restrict__ qkv,
                                                    float* __restrict__ att) {
    extern __shared__ float sm[];
    float* Ks = sm;
    float* Vs = sm + 4096;
    float* Sc = sm + 8192;

    int w = blockIdx.x;
    int h = blockIdx.y;
    int p = threadIdx.x;

    const float* rowp = qkv + (size_t)w * WS * 768 + (size_t)p * 768;
#pragma unroll
    for (int d = 0; d < DH; d += 4) {
        *(float4*)&Ks[p * 32 + d] = *(const float4*)&rowp[256 + h * 32 + d];
        *(float4*)&Vs[p * 32 + d] = *(const float4*)&rowp[512 + h * 32 + d];
    }
    float q[DH];
#pragma unroll
    for (int d = 0; d < DH; d += 4) {
        float4 v = *(const float4*)&rowp[h * 32 + d];
        q[d] = v.x; q[d + 1] = v.y; q[d + 2] = v.z; q[d + 3] = v.w;
    }
    __syncthreads();

    const float scale = 0.17677669529663687f;  // 1/sqrt(32)
    float m = -1e30f;
    for (int j = 0; j < WS; j++) {
        float s = 0.f;
#pragma unroll
        for (int d = 0; d < DH; d++) s += q[d] * Ks[j * 32 + d];
        s *= scale;
        Sc[p * 129 + j] = s;
        m = fmaxf(m, s);
    }
    float l = 0.f;
    float acc[DH];
#pragma unroll
    for (int d = 0; d < DH; d++) acc[d] = 0.f;
    for (int j = 0; j < WS; j++) {
        float e = __expf(Sc[p * 129 + j] - m);
        l += e;
#pragma unroll
        for (int d = 0; d < DH; d++) acc[d] += e * Vs[j * 32 + d];
    }
    float inv = 1.f / l;
    float* out = att + ((size_t)w * WS + p) * 256 + h * 32;
#pragma unroll
    for (int d = 0; d < DH; d += 4) {
        float4 o;
        o.x = acc[d] * inv;     o.y = acc[d + 1] * inv;
        o.z = acc[d + 2] * inv; o.w = acc[d + 3] * inv;
        *(float4*)&out[d] = o;
    }
}

// ---------------- fused residual add + LayerNorm -----------------------------
__global__ void add_ln_kernel(const float* __restrict__ resid,
                              const float* __restrict__ delta,
                              const float* __restrict__ gamma,
                              const float* __restrict__ beta,
                              float* __restrict__ out) {
    int row = blockIdx.x;
    int t = threadIdx.x;
    size_t idx = (size_t)row * 256 + t;
    float v = resid[idx] + delta[idx];

    __shared__ float red[8];
    float s = v;
#pragma unroll
    for (int o = 16; o > 0; o >>= 1) s += __shfl_xor_sync(0xffffffffu, s, o);
    if ((t & 31) == 0) red[t >> 5] = s;
    __syncthreads();
    if (t < 32) {
        float xr = (t < 8) ? red[t] : 0.f;
#pragma unroll
        for (int o = 4; o > 0; o >>= 1) xr += __shfl_xor_sync(0xffffffffu, xr, o);
        if (t == 0) red[0] = xr;
    }
    __syncthreads();
    float mean = red[0] * (1.f / 256.f);
    __syncthreads();

    float d = v - mean;
    float s2 = d * d;
#pragma unroll
    for (int o = 16; o > 0; o >>= 1) s2 += __shfl_xor_sync(0xffffffffu, s2, o);
    if ((t & 31) == 0) red[t >> 5] = s2;
    __syncthreads();
    if (t < 32) {
        float xr = (t < 8) ? red[t] : 0.f;
#pragma unroll
        for (int o = 4; o > 0; o >>= 1) xr += __shfl_xor_sync(0xffffffffu, xr, o);
        if (t == 0) red[0] = xr;
    }
    __syncthreads();
    float var = red[0] * (1.f / 256.f);
    out[idx] = d * rsqrtf(var + 1e-5f) * gamma[t] + beta[t];
}

// ---------------- launch ------------------------------------------------------
extern "C" void kernel_launch(void* const* d_in, const int* in_sizes, int n_in,
                              void* d_out, int out_size) {
    const int*   coords = (const int*)d_in[0];
    const float* feat   = (const float*)d_in[1];
    const float* pex    = (const float*)d_in[2];
    const float* pey    = (const float*)d_in[3];
    const float* pez    = (const float*)d_in[4];
    const float* pes    = (const float*)d_in[5];
    const float* Wqkv   = (const float*)d_in[6];
    const float* bqkv   = (const float*)d_in[7];
    const float* Wo     = (const float*)d_in[8];
    const float* bo     = (const float*)d_in[9];
    const float* W1     = (const float*)d_in[10];
    const float* b1     = (const float*)d_in[11];
    const float* W2     = (const float*)d_in[12];
    const float* b2     = (const float*)d_in[13];
    const float* g1     = (const float*)d_in[14];
    const float* be1    = (const float*)d_in[15];
    const float* g2     = (const float*)d_in[16];
    const float* be2    = (const float*)d_in[17];

    u64 *ka, *kb;
    float *xp, *qkvp, *attp, *tmpp, *ffp;
    cudaGetSymbolAddress((void**)&ka,   g_keysA);
    cudaGetSymbolAddress((void**)&kb,   g_keysB);
    cudaGetSymbolAddress((void**)&xp,   g_x);
    cudaGetSymbolAddress((void**)&qkvp, g_qkv);
    cudaGetSymbolAddress((void**)&attp, g_att);
    cudaGetSymbolAddress((void**)&tmpp, g_tmp);
    cudaGetSymbolAddress((void**)&ffp,  g_ff);

    static int attr_done = 0;
    const int gemm_smem = NSTAGE * 2 * STAGE_ELEMS * 4;  // 96 KB
    if (!attr_done) {
        cudaFuncSetAttribute(gemm_tf32_kernel,
                             cudaFuncAttributeMaxDynamicSharedMemorySize, gemm_smem);
        cudaFuncSetAttribute(attn2_kernel,
                             cudaFuncAttributeMaxDynamicSharedMemorySize, ATTN_SMEM);
        attr_done = 1;
    }

    // 1) morton keys + stable radix sort
    build_keys_kernel<<<256, 256>>>(coords, ka);
    int shifts[3] = {16, 24, 32};
    u64* src = ka;
    u64* dst = kb;
    for (int p = 0; p < 3; p++) {
        radix_hist_kernel<<<256, 256>>>(src, shifts[p]);
        radix_scan_kernel<<<1, 256>>>();
        radix_scatter_kernel<<<256, 256>>>(src, dst, shifts[p]);
        u64* t = src; src = dst; dst = t;
    }

    // 2) gather + positional embedding
    gather_pe_kernel<<<N_PTS, 256>>>(src, coords, feat, pex, pey, pez, pes, xp);

    // 3) transformer layers
    for (int l = 0; l < NLAYER; l++) {
        const float* wqkv = Wqkv + (size_t)l * 768 * 256;
        const float* bq   = bqkv + (size_t)l * 768;
        const float* wo   = Wo   + (size_t)l * 256 * 256;
        const float* bo_l = bo   + (size_t)l * 256;
        const float* w1   = W1   + (size_t)l * 2048 * 256;
        const float* b1_l = b1   + (size_t)l * 2048;
        const float* w2   = W2   + (size_t)l * 256 * 2048;
        const float* b2_l = b2   + (size_t)l * 256;

        gemm_tf32_kernel<<<dim3(768 / GBN, N_PTS / GBM), 256, gemm_smem>>>(
            xp, wqkv, bq, qkvp, N_PTS, 768, 256, 0);

        attn2_kernel<<<dim3(N_PTS / WS, NH), WS, ATTN_SMEM>>>(qkvp, attp);

        gemm_tf32_kernel<<<dim3(256 / GBN, N_PTS / GBM), 256, gemm_smem>>>(
            attp, wo, bo_l, tmpp, N_PTS, 256, 256, 0);

        add_ln_kernel<<<N_PTS, 256>>>(xp, tmpp, g1 + l * 256, be1 + l * 256, xp);

        gemm_tf32_kernel<<<dim3(2048 / GBN, N_PTS / GBM), 256, gemm_smem>>>(
            xp, w1, b1_l, ffp, N_PTS, 2048, 256, 1);

        gemm_tf32_kernel<<<dim3(256 / GBN, N_PTS / GBM), 256, gemm_smem>>>(
            ffp, w2, b2_l, tmpp, N_PTS, 256, 2048, 0);

        add_ln_kernel<<<N_PTS, 256>>>(xp, tmpp, g2 + l * 256, be2 + l * 256, xp);
    }

    // 4) output
    cudaMemcpyAsync(d_out, xp, (size_t)N_PTS * D_MODEL * sizeof(float),
                    cudaMemcpyDeviceToDevice);
}

// round 4
// speedup vs baseline: 2.9612x; 1.0538x over previous
#include <cuda_runtime.h>
#include <cstdint>
#include <cstddef>

typedef unsigned long long u64;
typedef unsigned int u32;

#define N_PTS   65536
#define D_MODEL 256
#define FF_DIM  2048
#define WS      128
#define NH      8
#define DH      32
#define NLAYER  4

// ---------------- scratch (static device globals; no runtime allocation) ----
__device__ u64 g_keysA[N_PTS];
__device__ u64 g_keysB[N_PTS];
__device__ u32 g_hist[256 * 256];
__device__ float g_x  [(size_t)N_PTS * D_MODEL];
__device__ float g_qkv[(size_t)N_PTS * 3 * D_MODEL];
__device__ float g_att[(size_t)N_PTS * D_MODEL];
__device__ float g_tmp[(size_t)N_PTS * D_MODEL];
__device__ float g_ff [(size_t)N_PTS * FF_DIM];
__device__ float g_w  [5242880];   // tf32-rounded weights (all layers)

#define WOFF_QKV 0
#define WOFF_O   786432
#define WOFF_1   1048576
#define WOFF_2   3145728

// ---------------- tf32 helpers ----------------------------------------------
__device__ __forceinline__ u32 f2tf32(float f) {
    u32 r;
    asm volatile("cvt.rna.tf32.f32 %0, %1;" : "=r"(r) : "f"(f));
    return r;
}
__device__ __forceinline__ float rnd_tf32(float f) {
    return __uint_as_float(f2tf32(f));
}

__global__ void cvt_tf32_kernel(const float* __restrict__ in, float* __restrict__ out, int n) {
    int i = blockIdx.x * 256 + threadIdx.x;
    if (i < n) out[i] = rnd_tf32(in[i]);
}

// ---------------- morton keys ------------------------------------------------
__global__ void build_keys_kernel(const int* __restrict__ coords, u64* __restrict__ keys) {
    int i = blockIdx.x * 256 + threadIdx.x;
    int b = coords[i * 4 + 0];
    int x = coords[i * 4 + 1];
    int y = coords[i * 4 + 2];
    int z = coords[i * 4 + 3];
    u32 m = 0;
#pragma unroll
    for (int k = 0; k < 7; k++) {
        m |= ((u32)((x >> k) & 1) << (3 * k + 2))
           | ((u32)((y >> k) & 1) << (3 * k + 1))
           | ((u32)((z >> k) & 1) << (3 * k));
    }
    u64 key = ((u64)b << 21) | (u64)m;
    keys[i] = (key << 16) | (u32)i;
}

// ---------------- stable LSD radix sort (3 passes over bits 16..39) ----------
__global__ void radix_hist_kernel(const u64* __restrict__ in, int shift) {
    __shared__ u32 h[256];
    int t = threadIdx.x, b = blockIdx.x;
    h[t] = 0;
    __syncthreads();
    u32 d = (u32)((in[b * 256 + t] >> shift) & 0xFF);
    atomicAdd(&h[d], 1u);
    __syncthreads();
    g_hist[t * 256 + b] = h[t];
}

__global__ void radix_scan_kernel() {
    __shared__ u32 dt[256];
    __shared__ u32 ex[256];
    int d = threadIdx.x;
    u32 s = 0;
    for (int b = 0; b < 256; b++) s += g_hist[d * 256 + b];
    dt[d] = s;
    __syncthreads();
    if (d == 0) {
        u32 run = 0;
        for (int i = 0; i < 256; i++) { ex[i] = run; run += dt[i]; }
    }
    __syncthreads();
    u32 run = ex[d];
    for (int b = 0; b < 256; b++) {
        u32 t = g_hist[d * 256 + b];
        g_hist[d * 256 + b] = run;
        run += t;
    }
}

__global__ void radix_scatter_kernel(const u64* __restrict__ in, u64* __restrict__ out, int shift) {
    __shared__ unsigned char digs[256];
    int t = threadIdx.x, b = blockIdx.x;
    u64 key = in[b * 256 + t];
    u32 d = (u32)((key >> shift) & 0xFF);
    digs[t] = (unsigned char)d;
    __syncthreads();
    int rank = 0;
    for (int j = 0; j < t; j++) rank += (digs[j] == (unsigned char)d);
    out[g_hist[d * 256 + b] + rank] = key;
}

// ---------------- gather + positional embedding (tf32-rounded output) --------
__global__ void gather_pe_kernel(const u64* __restrict__ keys,
                                 const int* __restrict__ coords,
                                 const float* __restrict__ feat,
                                 const float* __restrict__ pex,
                                 const float* __restrict__ pey,
                                 const float* __restrict__ pez,
                                 const float* __restrict__ pes,
                                 float* __restrict__ x) {
    int i = blockIdx.x;
    int t = threadIdx.x;
    int j = (int)(keys[i] & 0xFFFFu);
    int cx = coords[j * 4 + 1];
    int cy = coords[j * 4 + 2];
    int cz = coords[j * 4 + 3];
    float v = feat[(size_t)j * 256 + t]
            + pex[cx * 256 + t] + pey[cy * 256 + t]
            + pez[cz * 256 + t] + pes[256 + t];
    x[(size_t)i * 256 + t] = rnd_tf32(v);
}

// ---------------- tf32 mma.sync GEMM: C = A*B^T + bias -----------------------
// inputs MUST already be tf32-rounded (bits reinterpreted directly, no cvt)
#define GBM 128
#define GBN 128
#define GBK 32
#define NSTAGE 3
#define STAGE_ELEMS (GBM * GBK)

__device__ __forceinline__ void cp_async16(void* smem_dst, const void* gsrc) {
    u32 s = (u32)__cvta_generic_to_shared(smem_dst);
    asm volatile("cp.async.cg.shared.global [%0], [%1], 16;\n" :: "r"(s), "l"(gsrc));
}

__global__ __launch_bounds__(256) void gemm_tf32_kernel(
    const float* __restrict__ A, const float* __restrict__ B,
    const float* __restrict__ bias, float* __restrict__ C,
    int M, int Nn, int K, int relu, int rnd)
{
    extern __shared__ float smem[];
    float* As = smem;
    float* Bs = smem + NSTAGE * STAGE_ELEMS;

    int tid  = threadIdx.x;
    int lane = tid & 31;
    int warp = tid >> 5;
    int wm = warp & 1;
    int wn = warp >> 1;
    int m0 = blockIdx.y * GBM;
    int n0 = blockIdx.x * GBN;

    const float* Ag = A + (size_t)m0 * K;
    const float* Bg = B + (size_t)n0 * K;

    float c[4][4][4];
#pragma unroll
    for (int i = 0; i < 4; i++)
#pragma unroll
        for (int j = 0; j < 4; j++)
#pragma unroll
            for (int k = 0; k < 4; k++) c[i][j][k] = 0.f;

    const int KT = K / GBK;

    auto load_stage = [&](int tile) {
        if (tile < KT) {
            int k0 = tile * GBK;
            float* Ad = As + (tile % NSTAGE) * STAGE_ELEMS;
            float* Bd = Bs + (tile % NSTAGE) * STAGE_ELEMS;
#pragma unroll
            for (int i = 0; i < 4; i++) {
                int q   = tid + i * 256;
                int row = q >> 3;
                int c4  = q & 7;
                int soff = (row * 8 + (c4 ^ (row & 7))) * 4;
                cp_async16(Ad + soff, Ag + (size_t)row * K + k0 + c4 * 4);
                cp_async16(Bd + soff, Bg + (size_t)row * K + k0 + c4 * 4);
            }
        }
        asm volatile("cp.async.commit_group;");
    };

    load_stage(0);
    load_stage(1);

    for (int kt = 0; kt < KT; kt++) {
        asm volatile("cp.async.wait_group 1;");
        __syncthreads();
        load_stage(kt + 2);

        const u32* Ad = (const u32*)(As + (kt % NSTAGE) * STAGE_ELEMS);
        const u32* Bd = (const u32*)(Bs + (kt % NSTAGE) * STAGE_ELEMS);

#pragma unroll
        for (int ks = 0; ks < 4; ks++) {
            int kk  = ks * 8 + (lane & 3);
            int kk2 = kk + 4;
            int kc  = kk >> 2;
            int kc2 = kk2 >> 2;
            int r7  = lane >> 2;

            u32 af[4][4];
#pragma unroll
            for (int mt = 0; mt < 4; mt++) {
                int r  = wm * 64 + mt * 16 + (lane >> 2);
                int r2 = r + 8;
                af[mt][0] = Ad[(r  * 8 + (kc  ^ r7)) * 4 + (kk  & 3)];
                af[mt][1] = Ad[(r2 * 8 + (kc  ^ r7)) * 4 + (kk  & 3)];
                af[mt][2] = Ad[(r  * 8 + (kc2 ^ r7)) * 4 + (kk2 & 3)];
                af[mt][3] = Ad[(r2 * 8 + (kc2 ^ r7)) * 4 + (kk2 & 3)];
            }
            u32 bf[4][2];
#pragma unroll
            for (int nt = 0; nt < 4; nt++) {
                int n = wn * 32 + nt * 8 + (lane >> 2);
                bf[nt][0] = Bd[(n * 8 + (kc  ^ r7)) * 4 + (kk  & 3)];
                bf[nt][1] = Bd[(n * 8 + (kc2 ^ r7)) * 4 + (kk2 & 3)];
            }
#pragma unroll
            for (int mt = 0; mt < 4; mt++)
#pragma unroll
                for (int nt = 0; nt < 4; nt++) {
                    asm volatile(
                        "mma.sync.aligned.m16n8k8.row.col.f32.tf32.tf32.f32 "
                        "{%0,%1,%2,%3}, {%4,%5,%6,%7}, {%8,%9}, {%0,%1,%2,%3};"
                        : "+f"(c[mt][nt][0]), "+f"(c[mt][nt][1]),
                          "+f"(c[mt][nt][2]), "+f"(c[mt][nt][3])
                        : "r"(af[mt][0]), "r"(af[mt][1]), "r"(af[mt][2]), "r"(af[mt][3]),
                          "r"(bf[nt][0]), "r"(bf[nt][1]));
                }
        }
        __syncthreads();
    }

#pragma unroll
    for (int mt = 0; mt < 4; mt++) {
#pragma unroll
        for (int nt = 0; nt < 4; nt++) {
            int row = m0 + wm * 64 + mt * 16 + (lane >> 2);
            int col = n0 + wn * 32 + nt * 8 + (lane & 3) * 2;
            float2 bv = *(const float2*)(bias + col);
            float v0 = c[mt][nt][0] + bv.x;
            float v1 = c[mt][nt][1] + bv.y;
            float v2 = c[mt][nt][2] + bv.x;
            float v3 = c[mt][nt][3] + bv.y;
            if (relu) {
                v0 = fmaxf(v0, 0.f); v1 = fmaxf(v1, 0.f);
                v2 = fmaxf(v2, 0.f); v3 = fmaxf(v3, 0.f);
            }
            if (rnd) {
                v0 = rnd_tf32(v0); v1 = rnd_tf32(v1);
                v2 = rnd_tf32(v2); v3 = rnd_tf32(v3);
            }
            float2 o0 = {v0, v1};
            float2 o1 = {v2, v3};
            *(float2*)(C + (size_t)row * Nn + col) = o0;
            *(float2*)(C + (size_t)(row + 8) * Nn + col) = o1;
        }
    }
}

// ---------------- windowed attention: two-pass softmax, float4 LDS -----------
#define ATTN_SMEM ((4096 + 4096 + 128 * 132) * 4)
__global__ __launch_bounds__(128) void attn2_kernel(const float* __restrict__ qkv,
                                                    float* __restrict__ att) {
    extern __shared__ float sm[];
    float* Ks = sm;            // [128][32]
    float* Vs = sm + 4096;     // [128][32]
    float* Sc = sm + 8192;     // [128][132] padded

    int w = blockIdx.x;
    int h = blockIdx.y;
    int p = threadIdx.x;

    const float* rowp = qkv + (size_t)w * WS * 768 + (size_t)p * 768;
#pragma unroll
    for (int d = 0; d < DH; d += 4) {
        *(float4*)&Ks[p * 32 + d] = *(const float4*)&rowp[256 + h * 32 + d];
        *(float4*)&Vs[p * 32 + d] = *(const float4*)&rowp[512 + h * 32 + d];
    }
    float4 q4[8];
#pragma unroll
    for (int d = 0; d < 8; d++) q4[d] = *(const float4*)&rowp[h * 32 + d * 4];
    __syncthreads();

    const float scale = 0.17677669529663687f;  // 1/sqrt(32)
    float m = -1e30f;
    for (int j = 0; j < WS; j++) {
        const float4* kj = (const float4*)&Ks[j * 32];
        float s = 0.f;
#pragma unroll
        for (int d = 0; d < 8; d++) {
            float4 kv = kj[d];
            s = fmaf(q4[d].x, kv.x, s);
            s = fmaf(q4[d].y, kv.y, s);
            s = fmaf(q4[d].z, kv.z, s);
            s = fmaf(q4[d].w, kv.w, s);
        }
        s *= scale;
        Sc[p * 132 + j] = s;
        m = fmaxf(m, s);
    }
    float l = 0.f;
    float4 acc[8];
#pragma unroll
    for (int d = 0; d < 8; d++) acc[d] = make_float4(0.f, 0.f, 0.f, 0.f);
    for (int j = 0; j < WS; j++) {
        float e = __expf(Sc[p * 132 + j] - m);
        l += e;
        const float4* vj = (const float4*)&Vs[j * 32];
#pragma unroll
        for (int d = 0; d < 8; d++) {
            float4 vv = vj[d];
            acc[d].x = fmaf(e, vv.x, acc[d].x);
            acc[d].y = fmaf(e, vv.y, acc[d].y);
            acc[d].z = fmaf(e, vv.z, acc[d].z);
            acc[d].w = fmaf(e, vv.w, acc[d].w);
        }
    }
    float inv = 1.f / l;
    float* out = att + ((size_t)w * WS + p) * 256 + h * 32;
#pragma unroll
    for (int d = 0; d < 8; d++) {
        float4 o;
        o.x = rnd_tf32(acc[d].x * inv);
        o.y = rnd_tf32(acc[d].y * inv);
        o.z = rnd_tf32(acc[d].z * inv);
        o.w = rnd_tf32(acc[d].w * inv);
        *(float4*)&out[d * 4] = o;
    }
}

// ---------------- fused residual add + LayerNorm (tf32-rounded output) -------
__global__ void add_ln_kernel(const float* __restrict__ resid,
                              const float* __restrict__ delta,
                              const float* __restrict__ gamma,
                              const float* __restrict__ beta,
                              float* __restrict__ out) {
    int row = blockIdx.x;
    int t = threadIdx.x;
    size_t idx = (size_t)row * 256 + t;
    float v = resid[idx] + delta[idx];

    __shared__ float red[8];
    float s = v;
#pragma unroll
    for (int o = 16; o > 0; o >>= 1) s += __shfl_xor_sync(0xffffffffu, s, o);
    if ((t & 31) == 0) red[t >> 5] = s;
    __syncthreads();
    if (t < 32) {
        float xr = (t < 8) ? red[t] : 0.f;
#pragma unroll
        for (int o = 4; o > 0; o >>= 1) xr += __shfl_xor_sync(0xffffffffu, xr, o);
        if (t == 0) red[0] = xr;
    }
    __syncthreads();
    float mean = red[0] * (1.f / 256.f);
    __syncthreads();

    float d = v - mean;
    float s2 = d * d;
#pragma unroll
    for (int o = 16; o > 0; o >>= 1) s2 += __shfl_xor_sync(0xffffffffu, s2, o);
    if ((t & 31) == 0) red[t >> 5] = s2;
    __syncthreads();
    if (t < 32) {
        float xr = (t < 8) ? red[t] : 0.f;
#pragma unroll
        for (int o = 4; o > 0; o >>= 1) xr += __shfl_xor_sync(0xffffffffu, xr, o);
        if (t == 0) red[0] = xr;
    }
    __syncthreads();
    float var = red[0] * (1.f / 256.f);
    out[idx] = rnd_tf32(d * rsqrtf(var + 1e-5f) * gamma[t] + beta[t]);
}

// ---------------- launch ------------------------------------------------------
extern "C" void kernel_launch(void* const* d_in, const int* in_sizes, int n_in,
                              void* d_out, int out_size) {
    const int*   coords = (const int*)d_in[0];
    const float* feat   = (const float*)d_in[1];
    const float* pex    = (const float*)d_in[2];
    const float* pey    = (const float*)d_in[3];
    const float* pez    = (const float*)d_in[4];
    const float* pes    = (const float*)d_in[5];
    const float* Wqkv   = (const float*)d_in[6];
    const float* bqkv   = (const float*)d_in[7];
    const float* Wo     = (const float*)d_in[8];
    const float* bo     = (const float*)d_in[9];
    const float* W1     = (const float*)d_in[10];
    const float* b1     = (const float*)d_in[11];
    const float* W2     = (const float*)d_in[12];
    const float* b2     = (const float*)d_in[13];
    const float* g1     = (const float*)d_in[14];
    const float* be1    = (const float*)d_in[15];
    const float* g2     = (const float*)d_in[16];
    const float* be2    = (const float*)d_in[17];

    u64 *ka, *kb;
    float *xp, *qkvp, *attp, *tmpp, *ffp, *wp;
    cudaGetSymbolAddress((void**)&ka,   g_keysA);
    cudaGetSymbolAddress((void**)&kb,   g_keysB);
    cudaGetSymbolAddress((void**)&xp,   g_x);
    cudaGetSymbolAddress((void**)&qkvp, g_qkv);
    cudaGetSymbolAddress((void**)&attp, g_att);
    cudaGetSymbolAddress((void**)&tmpp, g_tmp);
    cudaGetSymbolAddress((void**)&ffp,  g_ff);
    cudaGetSymbolAddress((void**)&wp,   g_w);

    static int attr_done = 0;
    const int gemm_smem = NSTAGE * 2 * STAGE_ELEMS * 4;  // 96 KB
    if (!attr_done) {
        cudaFuncSetAttribute(gemm_tf32_kernel,
                             cudaFuncAttributeMaxDynamicSharedMemorySize, gemm_smem);
        cudaFuncSetAttribute(attn2_kernel,
                             cudaFuncAttributeMaxDynamicSharedMemorySize, ATTN_SMEM);
        attr_done = 1;
    }

    // 0) round all weights to tf32 (rna) once per call
    cvt_tf32_kernel<<<(786432  + 255) / 256, 256>>>(Wqkv, wp + WOFF_QKV, 786432);
    cvt_tf32_kernel<<<(262144  + 255) / 256, 256>>>(Wo,   wp + WOFF_O,   262144);
    cvt_tf32_kernel<<<(2097152 + 255) / 256, 256>>>(W1,   wp + WOFF_1,   2097152);
    cvt_tf32_kernel<<<(2097152 + 255) / 256, 256>>>(W2,   wp + WOFF_2,   2097152);

    // 1) morton keys + stable radix sort
    build_keys_kernel<<<256, 256>>>(coords, ka);
    int shifts[3] = {16, 24, 32};
    u64* src = ka;
    u64* dst = kb;
    for (int p = 0; p < 3; p++) {
        radix_hist_kernel<<<256, 256>>>(src, shifts[p]);
        radix_scan_kernel<<<1, 256>>>();
        radix_scatter_kernel<<<256, 256>>>(src, dst, shifts[p]);
        u64* t = src; src = dst; dst = t;
    }

    // 2) gather + positional embedding (tf32-rounded)
    gather_pe_kernel<<<N_PTS, 256>>>(src, coords, feat, pex, pey, pez, pes, xp);

    // 3) transformer layers
    for (int l = 0; l < NLAYER; l++) {
        const float* wqkv = wp + WOFF_QKV + (size_t)l * 768 * 256;
        const float* bq   = bqkv + (size_t)l * 768;
        const float* wo   = wp + WOFF_O + (size_t)l * 256 * 256;
        const float* bo_l = bo   + (size_t)l * 256;
        const float* w1   = wp + WOFF_1 + (size_t)l * 2048 * 256;
        const float* b1_l = b1   + (size_t)l * 2048;
        const float* w2   = wp + WOFF_2 + (size_t)l * 256 * 2048;
        const float* b2_l = b2   + (size_t)l * 256;

        // qkv = x @ Wqkv^T + bqkv   (x tf32-rounded; output fp32, feeds attention)
        gemm_tf32_kernel<<<dim3(768 / GBN, N_PTS / GBM), 256, gemm_smem>>>(
            xp, wqkv, bq, qkvp, N_PTS, 768, 256, 0, 0);

        attn2_kernel<<<dim3(N_PTS / WS, NH), WS, ATTN_SMEM>>>(qkvp, attp);

        // o = att @ Wo^T + bo  (att tf32-rounded)
        gemm_tf32_kernel<<<dim3(256 / GBN, N_PTS / GBM), 256, gemm_smem>>>(
            attp, wo, bo_l, tmpp, N_PTS, 256, 256, 0, 0);

        add_ln_kernel<<<N_PTS, 256>>>(xp, tmpp, g1 + l * 256, be1 + l * 256, xp);

        // ff = relu(x @ W1^T + b1)  (round output: feeds FF2 GEMM)
        gemm_tf32_kernel<<<dim3(2048 / GBN, N_PTS / GBM), 256, gemm_smem>>>(
            xp, w1, b1_l, ffp, N_PTS, 2048, 256, 1, 1);

        gemm_tf32_kernel<<<dim3(256 / GBN, N_PTS / GBM), 256, gemm_smem>>>(
            ffp, w2, b2_l, tmpp, N_PTS, 256, 2048, 0, 0);

        add_ln_kernel<<<N_PTS, 256>>>(xp, tmpp, g2 + l * 256, be2 + l * 256, xp);
    }

    // 4) output
    cudaMemcpyAsync(d_out, xp, (size_t)N_PTS * D_MODEL * sizeof(float),
                    cudaMemcpyDeviceToDevice);
}

// round 5
// speedup vs baseline: 4.0437x; 1.3656x over previous
#include <cuda_runtime.h>
#include <cuda_fp16.h>
#include <cstdint>
#include <cstddef>

typedef unsigned long long u64;
typedef unsigned int u32;

#define N_PTS   65536
#define D_MODEL 256
#define FF_DIM  2048
#define WS      128
#define NH      8
#define DH      32
#define NLAYER  4

// ---------------- scratch (static device globals; no runtime allocation) ----
__device__ u64 g_keysA[N_PTS];
__device__ u64 g_keysB[N_PTS];
__device__ u32 g_hist[256 * 256];
__device__ float  g_x   [(size_t)N_PTS * D_MODEL];      // fp32 residual stream
__device__ float  g_qkv [(size_t)N_PTS * 3 * D_MODEL];  // fp32 (attention input)
__device__ float  g_tmp [(size_t)N_PTS * D_MODEL];      // fp32 GEMM outputs
__device__ __half g_x16 [(size_t)N_PTS * D_MODEL];      // fp16 GEMM A-inputs
__device__ __half g_att16[(size_t)N_PTS * D_MODEL];
__device__ __half g_ff16[(size_t)N_PTS * FF_DIM];
__device__ __half g_w16 [5242880];                      // all weights, fp16

#define WOFF_QKV 0
#define WOFF_O   786432
#define WOFF_1   1048576
#define WOFF_2   3145728

// ---------------- fp32 -> fp16 weight conversion -----------------------------
__global__ void cvt_f16_kernel(const float* __restrict__ in, __half* __restrict__ out, int n) {
    int i = blockIdx.x * 256 + threadIdx.x;
    if (i < n) out[i] = __float2half_rn(in[i]);
}

// ---------------- morton keys ------------------------------------------------
__global__ void build_keys_kernel(const int* __restrict__ coords, u64* __restrict__ keys) {
    int i = blockIdx.x * 256 + threadIdx.x;
    int b = coords[i * 4 + 0];
    int x = coords[i * 4 + 1];
    int y = coords[i * 4 + 2];
    int z = coords[i * 4 + 3];
    u32 m = 0;
#pragma unroll
    for (int k = 0; k < 7; k++) {
        m |= ((u32)((x >> k) & 1) << (3 * k + 2))
           | ((u32)((y >> k) & 1) << (3 * k + 1))
           | ((u32)((z >> k) & 1) << (3 * k));
    }
    u64 key = ((u64)b << 21) | (u64)m;
    keys[i] = (key << 16) | (u32)i;
}

// ---------------- stable LSD radix sort (3 passes over bits 16..39) ----------
__global__ void radix_hist_kernel(const u64* __restrict__ in, int shift) {
    __shared__ u32 h[256];
    int t = threadIdx.x, b = blockIdx.x;
    h[t] = 0;
    __syncthreads();
    u32 d = (u32)((in[b * 256 + t] >> shift) & 0xFF);
    atomicAdd(&h[d], 1u);
    __syncthreads();
    g_hist[t * 256 + b] = h[t];
}

__global__ void radix_scan_kernel() {
    __shared__ u32 dt[256];
    __shared__ u32 ex[256];
    int d = threadIdx.x;
    u32 s = 0;
    for (int b = 0; b < 256; b++) s += g_hist[d * 256 + b];
    dt[d] = s;
    __syncthreads();
    if (d == 0) {
        u32 run = 0;
        for (int i = 0; i < 256; i++) { ex[i] = run; run += dt[i]; }
    }
    __syncthreads();
    u32 run = ex[d];
    for (int b = 0; b < 256; b++) {
        u32 t = g_hist[d * 256 + b];
        g_hist[d * 256 + b] = run;
        run += t;
    }
}

__global__ void radix_scatter_kernel(const u64* __restrict__ in, u64* __restrict__ out, int shift) {
    __shared__ unsigned char digs[256];
    int t = threadIdx.x, b = blockIdx.x;
    u64 key = in[b * 256 + t];
    u32 d = (u32)((key >> shift) & 0xFF);
    digs[t] = (unsigned char)d;
    __syncthreads();
    int rank = 0;
    for (int j = 0; j < t; j++) rank += (digs[j] == (unsigned char)d);
    out[g_hist[d * 256 + b] + rank] = key;
}

// ---------------- gather + PE: fp32 residual + fp16 GEMM copy ----------------
__global__ void gather_pe_kernel(const u64* __restrict__ keys,
                                 const int* __restrict__ coords,
                                 const float* __restrict__ feat,
                                 const float* __restrict__ pex,
                                 const float* __restrict__ pey,
                                 const float* __restrict__ pez,
                                 const float* __restrict__ pes,
                                 float* __restrict__ x,
                                 __half* __restrict__ x16) {
    int i = blockIdx.x;
    int t = threadIdx.x;
    int j = (int)(keys[i] & 0xFFFFu);
    int cx = coords[j * 4 + 1];
    int cy = coords[j * 4 + 2];
    int cz = coords[j * 4 + 3];
    float v = feat[(size_t)j * 256 + t]
            + pex[cx * 256 + t] + pey[cy * 256 + t]
            + pez[cz * 256 + t] + pes[256 + t];
    x[(size_t)i * 256 + t]   = v;
    x16[(size_t)i * 256 + t] = __float2half_rn(v);
}

// ---------------- fp16 mma.sync GEMM: C[M,N] = A[M,K]*B[N,K]^T + bias --------
// A, B fp16 (pre-rounded); accumulate fp32; out fp32 OR fp16(+relu)
#define GBM 128
#define GBN 128
#define GBK 64
#define NSTAGE 3
#define ASTAGE_BYTES (GBM * GBK * 2)                 // 16384
#define STAGE_BYTES  (ASTAGE_BYTES * 2)              // 32768 (A+B)
#define GEMM_SMEM    (NSTAGE * STAGE_BYTES)          // 98304

__device__ __forceinline__ void cp_async16h(u32 saddr, const void* g) {
    asm volatile("cp.async.cg.shared.global [%0], [%1], 16;" :: "r"(saddr), "l"(g));
}
__device__ __forceinline__ void ldsm4(u32& r0, u32& r1, u32& r2, u32& r3, u32 addr) {
    asm volatile("ldmatrix.sync.aligned.m8n8.x4.shared.b16 {%0,%1,%2,%3}, [%4];"
                 : "=r"(r0), "=r"(r1), "=r"(r2), "=r"(r3) : "r"(addr));
}

__global__ __launch_bounds__(256) void gemm_f16_kernel(
    const __half* __restrict__ A, const __half* __restrict__ B,
    const float* __restrict__ bias, float* __restrict__ C32,
    __half* __restrict__ C16, int Nn, int K, int out16relu)
{
    extern __shared__ char smem_raw[];
    u32 sbase = (u32)__cvta_generic_to_shared(smem_raw);

    int tid  = threadIdx.x;
    int lane = tid & 31;
    int warp = tid >> 5;
    int wm = warp & 1;          // 2 warp rows x 64
    int wn = warp >> 1;         // 4 warp cols x 32
    int m0 = blockIdx.y * GBM;
    int n0 = blockIdx.x * GBN;

    const __half* Ag = A + (size_t)m0 * K;
    const __half* Bg = B + (size_t)n0 * K;

    float c[4][4][4];
#pragma unroll
    for (int i = 0; i < 4; i++)
#pragma unroll
        for (int j = 0; j < 4; j++)
#pragma unroll
            for (int k = 0; k < 4; k++) c[i][j][k] = 0.f;

    const int KT = K / GBK;

    // one stage: A tile 128x64h + B tile 128x64h; 16B chunks, XOR swizzle
    auto load_stage = [&](int tile) {
        if (tile < KT) {
            int k0 = tile * GBK;
            u32 sa = sbase + (u32)(tile % NSTAGE) * STAGE_BYTES;
            u32 sb = sa + ASTAGE_BYTES;
#pragma unroll
            for (int i = 0; i < 4; i++) {
                int q = tid + i * 256;         // 0..1023
                int r = q >> 3, ch = q & 7;
                u32 off = (u32)(r * 8 + (ch ^ (r & 7))) * 16u;
                cp_async16h(sa + off, Ag + (size_t)r * K + k0 + ch * 8);
                cp_async16h(sb + off, Bg + (size_t)r * K + k0 + ch * 8);
            }
        }
        asm volatile("cp.async.commit_group;");
    };

    load_stage(0);
    load_stage(1);

    int idx   = lane >> 3;            // ldmatrix matrix id
    int lrow  = lane & 7;
    int a_mo  = (idx & 1) * 8;        // A: m0k0, m8k0, m0k8, m8k8
    int a_kc  = idx >> 1;
    int b_no  = (idx >> 1) * 8;       // B: n0k0, n0k8, n8k0, n8k8
    int b_kc  = idx & 1;

    for (int kt = 0; kt < KT; kt++) {
        asm volatile("cp.async.wait_group 1;");
        __syncthreads();
        load_stage(kt + 2);

        u32 sa = sbase + (u32)(kt % NSTAGE) * STAGE_BYTES;
        u32 sb = sa + ASTAGE_BYTES;

#pragma unroll
        for (int ks = 0; ks < 4; ks++) {      // 4 ksteps of k16
            u32 a[4][4];
#pragma unroll
            for (int mt = 0; mt < 4; mt++) {
                int r  = wm * 64 + mt * 16 + a_mo + lrow;
                int ch = ks * 2 + a_kc;
                ldsm4(a[mt][0], a[mt][1], a[mt][2], a[mt][3],
                      sa + (u32)(r * 8 + (ch ^ (r & 7))) * 16u);
            }
            u32 b[4][2];
#pragma unroll
            for (int nt2 = 0; nt2 < 2; nt2++) {
                int r  = wn * 32 + nt2 * 16 + b_no + lrow;
                int ch = ks * 2 + b_kc;
                u32 t0, t1, t2, t3;
                ldsm4(t0, t1, t2, t3, sb + (u32)(r * 8 + (ch ^ (r & 7))) * 16u);
                b[nt2 * 2][0] = t0; b[nt2 * 2][1] = t1;
                b[nt2 * 2 + 1][0] = t2; b[nt2 * 2 + 1][1] = t3;
            }
#pragma unroll
            for (int mt = 0; mt < 4; mt++)
#pragma unroll
                for (int nt = 0; nt < 4; nt++) {
                    asm volatile(
                        "mma.sync.aligned.m16n8k16.row.col.f32.f16.f16.f32 "
                        "{%0,%1,%2,%3}, {%4,%5,%6,%7}, {%8,%9}, {%0,%1,%2,%3};"
                        : "+f"(c[mt][nt][0]), "+f"(c[mt][nt][1]),
                          "+f"(c[mt][nt][2]), "+f"(c[mt][nt][3])
                        : "r"(a[mt][0]), "r"(a[mt][1]), "r"(a[mt][2]), "r"(a[mt][3]),
                          "r"(b[nt][0]), "r"(b[nt][1]));
                }
        }
        __syncthreads();
    }

#pragma unroll
    for (int mt = 0; mt < 4; mt++) {
#pragma unroll
        for (int nt = 0; nt < 4; nt++) {
            int row = m0 + wm * 64 + mt * 16 + (lane >> 2);
            int col = n0 + wn * 32 + nt * 8 + (lane & 3) * 2;
            float2 bv = *(const float2*)(bias + col);
            float v0 = c[mt][nt][0] + bv.x;
            float v1 = c[mt][nt][1] + bv.y;
            float v2 = c[mt][nt][2] + bv.x;
            float v3 = c[mt][nt][3] + bv.y;
            if (out16relu) {
                v0 = fmaxf(v0, 0.f); v1 = fmaxf(v1, 0.f);
                v2 = fmaxf(v2, 0.f); v3 = fmaxf(v3, 0.f);
                *(__half2*)(C16 + (size_t)row * Nn + col) = __floats2half2_rn(v0, v1);
                *(__half2*)(C16 + (size_t)(row + 8) * Nn + col) = __floats2half2_rn(v2, v3);
            } else {
                float2 o0 = {v0, v1};
                float2 o1 = {v2, v3};
                *(float2*)(C32 + (size_t)row * Nn + col) = o0;
                *(float2*)(C32 + (size_t)(row + 8) * Nn + col) = o1;
            }
        }
    }
}

// ---------------- windowed attention: fp32 math, fp16 output -----------------
#define ATTN_SMEM ((4096 + 4096 + 128 * 132) * 4)
__global__ __launch_bounds__(128) void attn2_kernel(const float* __restrict__ qkv,
                                                    __half* __restrict__ att16) {
    extern __shared__ float sm[];
    float* Ks = sm;            // [128][32]
    float* Vs = sm + 4096;     // [128][32]
    float* Sc = sm + 8192;     // [128][132]

    int w = blockIdx.x;
    int h = blockIdx.y;
    int p = threadIdx.x;

    const float* rowp = qkv + (size_t)w * WS * 768 + (size_t)p * 768;
#pragma unroll
    for (int d = 0; d < DH; d += 4) {
        *(float4*)&Ks[p * 32 + d] = *(const float4*)&rowp[256 + h * 32 + d];
        *(float4*)&Vs[p * 32 + d] = *(const float4*)&rowp[512 + h * 32 + d];
    }
    float4 q4[8];
#pragma unroll
    for (int d = 0; d < 8; d++) q4[d] = *(const float4*)&rowp[h * 32 + d * 4];
    __syncthreads();

    const float scale = 0.17677669529663687f;
    float m = -1e30f;
    for (int j = 0; j < WS; j++) {
        const float4* kj = (const float4*)&Ks[j * 32];
        float s = 0.f;
#pragma unroll
        for (int d = 0; d < 8; d++) {
            float4 kv = kj[d];
            s = fmaf(q4[d].x, kv.x, s);
            s = fmaf(q4[d].y, kv.y, s);
            s = fmaf(q4[d].z, kv.z, s);
            s = fmaf(q4[d].w, kv.w, s);
        }
        s *= scale;
        Sc[p * 132 + j] = s;
        m = fmaxf(m, s);
    }
    float l = 0.f;
    float4 acc[8];
#pragma unroll
    for (int d = 0; d < 8; d++) acc[d] = make_float4(0.f, 0.f, 0.f, 0.f);
    for (int j = 0; j < WS; j++) {
        float e = __expf(Sc[p * 132 + j] - m);
        l += e;
        const float4* vj = (const float4*)&Vs[j * 32];
#pragma unroll
        for (int d = 0; d < 8; d++) {
            float4 vv = vj[d];
            acc[d].x = fmaf(e, vv.x, acc[d].x);
            acc[d].y = fmaf(e, vv.y, acc[d].y);
            acc[d].z = fmaf(e, vv.z, acc[d].z);
            acc[d].w = fmaf(e, vv.w, acc[d].w);
        }
    }
    float inv = 1.f / l;
    __half2* out2 = (__half2*)(att16 + ((size_t)w * WS + p) * 256 + h * 32);
#pragma unroll
    for (int d = 0; d < 8; d++) {
        out2[d * 2]     = __floats2half2_rn(acc[d].x * inv, acc[d].y * inv);
        out2[d * 2 + 1] = __floats2half2_rn(acc[d].z * inv, acc[d].w * inv);
    }
}

// ---------------- residual add + LayerNorm: fp32 out + fp16 copy -------------
__global__ void add_ln_kernel(const float* __restrict__ resid,
                              const float* __restrict__ delta,
                              const float* __restrict__ gamma,
                              const float* __restrict__ beta,
                              float* __restrict__ out,
                              __half* __restrict__ out16) {
    int row = blockIdx.x;
    int t = threadIdx.x;
    size_t idx = (size_t)row * 256 + t;
    float v = resid[idx] + delta[idx];

    __shared__ float red[8];
    float s = v;
#pragma unroll
    for (int o = 16; o > 0; o >>= 1) s += __shfl_xor_sync(0xffffffffu, s, o);
    if ((t & 31) == 0) red[t >> 5] = s;
    __syncthreads();
    if (t < 32) {
        float xr = (t < 8) ? red[t] : 0.f;
#pragma unroll
        for (int o = 4; o > 0; o >>= 1) xr += __shfl_xor_sync(0xffffffffu, xr, o);
        if (t == 0) red[0] = xr;
    }
    __syncthreads();
    float mean = red[0] * (1.f / 256.f);
    __syncthreads();

    float d = v - mean;
    float s2 = d * d;
#pragma unroll
    for (int o = 16; o > 0; o >>= 1) s2 += __shfl_xor_sync(0xffffffffu, s2, o);
    if ((t & 31) == 0) red[t >> 5] = s2;
    __syncthreads();
    if (t < 32) {
        float xr = (t < 8) ? red[t] : 0.f;
#pragma unroll
        for (int o = 4; o > 0; o >>= 1) xr += __shfl_xor_sync(0xffffffffu, xr, o);
        if (t == 0) red[0] = xr;
    }
    __syncthreads();
    float var = red[0] * (1.f / 256.f);
    float r = d * rsqrtf(var + 1e-5f) * gamma[t] + beta[t];
    out[idx] = r;
    out16[idx] = __float2half_rn(r);
}

// ---------------- launch ------------------------------------------------------
extern "C" void kernel_launch(void* const* d_in, const int* in_sizes, int n_in,
                              void* d_out, int out_size) {
    const int*   coords = (const int*)d_in[0];
    const float* feat   = (const float*)d_in[1];
    const float* pex    = (const float*)d_in[2];
    const float* pey    = (const float*)d_in[3];
    const float* pez    = (const float*)d_in[4];
    const float* pes    = (const float*)d_in[5];
    const float* Wqkv   = (const float*)d_in[6];
    const float* bqkv   = (const float*)d_in[7];
    const float* Wo     = (const float*)d_in[8];
    const float* bo     = (const float*)d_in[9];
    const float* W1     = (const float*)d_in[10];
    const float* b1     = (const float*)d_in[11];
    const float* W2     = (const float*)d_in[12];
    const float* b2     = (const float*)d_in[13];
    const float* g1     = (const float*)d_in[14];
    const float* be1    = (const float*)d_in[15];
    const float* g2     = (const float*)d_in[16];
    const float* be2    = (const float*)d_in[17];

    u64 *ka, *kb;
    float *xp, *qkvp, *tmpp;
    __half *x16p, *att16p, *ff16p, *w16p;
    cudaGetSymbolAddress((void**)&ka,    g_keysA);
    cudaGetSymbolAddress((void**)&kb,    g_keysB);
    cudaGetSymbolAddress((void**)&xp,    g_x);
    cudaGetSymbolAddress((void**)&qkvp,  g_qkv);
    cudaGetSymbolAddress((void**)&tmpp,  g_tmp);
    cudaGetSymbolAddress((void**)&x16p,  g_x16);
    cudaGetSymbolAddress((void**)&att16p,g_att16);
    cudaGetSymbolAddress((void**)&ff16p, g_ff16);
    cudaGetSymbolAddress((void**)&w16p,  g_w16);

    static int attr_done = 0;
    if (!attr_done) {
        cudaFuncSetAttribute(gemm_f16_kernel,
                             cudaFuncAttributeMaxDynamicSharedMemorySize, GEMM_SMEM);
        cudaFuncSetAttribute(attn2_kernel,
                             cudaFuncAttributeMaxDynamicSharedMemorySize, ATTN_SMEM);
        attr_done = 1;
    }

    // 0) weights -> fp16 once per call
    cvt_f16_kernel<<<(786432  + 255) / 256, 256>>>(Wqkv, w16p + WOFF_QKV, 786432);
    cvt_f16_kernel<<<(262144  + 255) / 256, 256>>>(Wo,   w16p + WOFF_O,   262144);
    cvt_f16_kernel<<<(2097152 + 255) / 256, 256>>>(W1,   w16p + WOFF_1,   2097152);
    cvt_f16_kernel<<<(2097152 + 255) / 256, 256>>>(W2,   w16p + WOFF_2,   2097152);

    // 1) morton keys + stable radix sort
    build_keys_kernel<<<256, 256>>>(coords, ka);
    int shifts[3] = {16, 24, 32};
    u64* src = ka;
    u64* dst = kb;
    for (int p = 0; p < 3; p++) {
        radix_hist_kernel<<<256, 256>>>(src, shifts[p]);
        radix_scan_kernel<<<1, 256>>>();
        radix_scatter_kernel<<<256, 256>>>(src, dst, shifts[p]);
        u64* t = src; src = dst; dst = t;
    }

    // 2) gather + positional embedding
    gather_pe_kernel<<<N_PTS, 256>>>(src, coords, feat, pex, pey, pez, pes, xp, x16p);

    // 3) transformer layers
    for (int l = 0; l < NLAYER; l++) {
        const __half* wqkv = w16p + WOFF_QKV + (size_t)l * 768 * 256;
        const float*  bq   = bqkv + (size_t)l * 768;
        const __half* wo   = w16p + WOFF_O + (size_t)l * 256 * 256;
        const float*  bo_l = bo   + (size_t)l * 256;
        const __half* w1   = w16p + WOFF_1 + (size_t)l * 2048 * 256;
        const float*  b1_l = b1   + (size_t)l * 2048;
        const __half* w2   = w16p + WOFF_2 + (size_t)l * 256 * 2048;
        const float*  b2_l = b2   + (size_t)l * 256;

        // qkv = x16 @ Wqkv^T + bqkv -> fp32 (attention input)
        gemm_f16_kernel<<<dim3(768 / GBN, N_PTS / GBM), 256, GEMM_SMEM>>>(
            x16p, wqkv, bq, qkvp, nullptr, 768, 256, 0);

        attn2_kernel<<<dim3(N_PTS / WS, NH), WS, ATTN_SMEM>>>(qkvp, att16p);

        // o = att16 @ Wo^T + bo -> fp32
        gemm_f16_kernel<<<dim3(256 / GBN, N_PTS / GBM), 256, GEMM_SMEM>>>(
            att16p, wo, bo_l, tmpp, nullptr, 256, 256, 0);

        add_ln_kernel<<<N_PTS, 256>>>(xp, tmpp, g1 + l * 256, be1 + l * 256, xp, x16p);

        // ff = relu(x16 @ W1^T + b1) -> fp16
        gemm_f16_kernel<<<dim3(2048 / GBN, N_PTS / GBM), 256, GEMM_SMEM>>>(
            x16p, w1, b1_l, nullptr, ff16p, 2048, 256, 1);

        // out = ff16 @ W2^T + b2 -> fp32
        gemm_f16_kernel<<<dim3(256 / GBN, N_PTS / GBM), 256, GEMM_SMEM>>>(
            ff16p, w2, b2_l, tmpp, nullptr, 256, 2048, 0);

        add_ln_kernel<<<N_PTS, 256>>>(xp, tmpp, g2 + l * 256, be2 + l * 256, xp, x16p);
    }

    // 4) output
    cudaMemcpyAsync(d_out, xp, (size_t)N_PTS * D_MODEL * sizeof(float),
                    cudaMemcpyDeviceToDevice);
}

// round 6
// speedup vs baseline: 5.9552x; 1.4727x over previous
#include <cuda_runtime.h>
#include <cuda_fp16.h>
#include <cstdint>
#include <cstddef>

typedef unsigned long long u64;
typedef unsigned int u32;

#define N_PTS   65536
#define D_MODEL 256
#define FF_DIM  2048
#define WS      128
#define NH      8
#define DH      32
#define NLAYER  4

// ---------------- scratch ----------------------------------------------------
__device__ u64 g_keysA[N_PTS];
__device__ u64 g_keysB[N_PTS];
__device__ u32 g_hist[256 * 256];
__device__ float  g_x   [(size_t)N_PTS * D_MODEL];      // fp32 residual stream
__device__ float  g_tmp [(size_t)N_PTS * D_MODEL];      // fp32 GEMM outputs
__device__ __half g_qkv16[(size_t)N_PTS * 3 * D_MODEL]; // fp16 qkv
__device__ __half g_x16 [(size_t)N_PTS * D_MODEL];
__device__ __half g_att16[(size_t)N_PTS * D_MODEL];
__device__ __half g_ff16[(size_t)N_PTS * FF_DIM];
__device__ __half g_w16 [5242880];

#define WOFF_QKV 0
#define WOFF_O   786432
#define WOFF_1   1048576
#define WOFF_2   3145728

__global__ void cvt_f16_kernel(const float* __restrict__ in, __half* __restrict__ out, int n) {
    int i = blockIdx.x * 256 + threadIdx.x;
    if (i < n) out[i] = __float2half_rn(in[i]);
}

// ---------------- morton keys ------------------------------------------------
__global__ void build_keys_kernel(const int* __restrict__ coords, u64* __restrict__ keys) {
    int i = blockIdx.x * 256 + threadIdx.x;
    int b = coords[i * 4 + 0];
    int x = coords[i * 4 + 1];
    int y = coords[i * 4 + 2];
    int z = coords[i * 4 + 3];
    u32 m = 0;
#pragma unroll
    for (int k = 0; k < 7; k++) {
        m |= ((u32)((x >> k) & 1) << (3 * k + 2))
           | ((u32)((y >> k) & 1) << (3 * k + 1))
           | ((u32)((z >> k) & 1) << (3 * k));
    }
    u64 key = ((u64)b << 21) | (u64)m;
    keys[i] = (key << 16) | (u32)i;
}

// ---------------- stable LSD radix sort --------------------------------------
__global__ void radix_hist_kernel(const u64* __restrict__ in, int shift) {
    __shared__ u32 h[256];
    int t = threadIdx.x, b = blockIdx.x;
    h[t] = 0;
    __syncthreads();
    u32 d = (u32)((in[b * 256 + t] >> shift) & 0xFF);
    atomicAdd(&h[d], 1u);
    __syncthreads();
    g_hist[t * 256 + b] = h[t];
}

__global__ void radix_scan_kernel() {
    __shared__ u32 dt[256];
    __shared__ u32 ex[256];
    int d = threadIdx.x;
    u32 s = 0;
    for (int b = 0; b < 256; b++) s += g_hist[d * 256 + b];
    dt[d] = s;
    __syncthreads();
    if (d == 0) {
        u32 run = 0;
        for (int i = 0; i < 256; i++) { ex[i] = run; run += dt[i]; }
    }
    __syncthreads();
    u32 run = ex[d];
    for (int b = 0; b < 256; b++) {
        u32 t = g_hist[d * 256 + b];
        g_hist[d * 256 + b] = run;
        run += t;
    }
}

__global__ void radix_scatter_kernel(const u64* __restrict__ in, u64* __restrict__ out, int shift) {
    __shared__ unsigned char digs[256];
    int t = threadIdx.x, b = blockIdx.x;
    u64 key = in[b * 256 + t];
    u32 d = (u32)((key >> shift) & 0xFF);
    digs[t] = (unsigned char)d;
    __syncthreads();
    int rank = 0;
    for (int j = 0; j < t; j++) rank += (digs[j] == (unsigned char)d);
    out[g_hist[d * 256 + b] + rank] = key;
}

// ---------------- gather + PE ------------------------------------------------
__global__ void gather_pe_kernel(const u64* __restrict__ keys,
                                 const int* __restrict__ coords,
                                 const float* __restrict__ feat,
                                 const float* __restrict__ pex,
                                 const float* __restrict__ pey,
                                 const float* __restrict__ pez,
                                 const float* __restrict__ pes,
                                 float* __restrict__ x,
                                 __half* __restrict__ x16) {
    int i = blockIdx.x;
    int t = threadIdx.x;
    int j = (int)(keys[i] & 0xFFFFu);
    int cx = coords[j * 4 + 1];
    int cy = coords[j * 4 + 2];
    int cz = coords[j * 4 + 3];
    float v = feat[(size_t)j * 256 + t]
            + pex[cx * 256 + t] + pey[cy * 256 + t]
            + pez[cz * 256 + t] + pes[256 + t];
    x[(size_t)i * 256 + t]   = v;
    x16[(size_t)i * 256 + t] = __float2half_rn(v);
}

// ---------------- fp16 mma.sync GEMM (unchanged core, out modes) -------------
#define GBM 128
#define GBN 128
#define GBK 64
#define NSTAGE 3
#define ASTAGE_BYTES (GBM * GBK * 2)
#define STAGE_BYTES  (ASTAGE_BYTES * 2)
#define GEMM_SMEM    (NSTAGE * STAGE_BYTES)

__device__ __forceinline__ void cp_async16h(u32 saddr, const void* g) {
    asm volatile("cp.async.cg.shared.global [%0], [%1], 16;" :: "r"(saddr), "l"(g));
}
__device__ __forceinline__ void ldsm4(u32& r0, u32& r1, u32& r2, u32& r3, u32 addr) {
    asm volatile("ldmatrix.sync.aligned.m8n8.x4.shared.b16 {%0,%1,%2,%3}, [%4];"
                 : "=r"(r0), "=r"(r1), "=r"(r2), "=r"(r3) : "r"(addr));
}
__device__ __forceinline__ void mma16816(float* c, const u32* a, const u32* b) {
    asm volatile(
        "mma.sync.aligned.m16n8k16.row.col.f32.f16.f16.f32 "
        "{%0,%1,%2,%3}, {%4,%5,%6,%7}, {%8,%9}, {%0,%1,%2,%3};"
        : "+f"(c[0]), "+f"(c[1]), "+f"(c[2]), "+f"(c[3])
        : "r"(a[0]), "r"(a[1]), "r"(a[2]), "r"(a[3]), "r"(b[0]), "r"(b[1]));
}

// mode: 0 = fp32 out, 1 = fp16 out, 2 = fp16 out + relu
__global__ __launch_bounds__(256) void gemm_f16_kernel(
    const __half* __restrict__ A, const __half* __restrict__ B,
    const float* __restrict__ bias, float* __restrict__ C32,
    __half* __restrict__ C16, int Nn, int K, int mode)
{
    extern __shared__ char smem_raw[];
    u32 sbase = (u32)__cvta_generic_to_shared(smem_raw);

    int tid  = threadIdx.x;
    int lane = tid & 31;
    int warp = tid >> 5;
    int wm = warp & 1;
    int wn = warp >> 1;
    int m0 = blockIdx.y * GBM;
    int n0 = blockIdx.x * GBN;

    const __half* Ag = A + (size_t)m0 * K;
    const __half* Bg = B + (size_t)n0 * K;

    float c[4][4][4];
#pragma unroll
    for (int i = 0; i < 4; i++)
#pragma unroll
        for (int j = 0; j < 4; j++)
#pragma unroll
            for (int k = 0; k < 4; k++) c[i][j][k] = 0.f;

    const int KT = K / GBK;

    auto load_stage = [&](int tile) {
        if (tile < KT) {
            int k0 = tile * GBK;
            u32 sa = sbase + (u32)(tile % NSTAGE) * STAGE_BYTES;
            u32 sb = sa + ASTAGE_BYTES;
#pragma unroll
            for (int i = 0; i < 4; i++) {
                int q = tid + i * 256;
                int r = q >> 3, ch = q & 7;
                u32 off = (u32)(r * 8 + (ch ^ (r & 7))) * 16u;
                cp_async16h(sa + off, Ag + (size_t)r * K + k0 + ch * 8);
                cp_async16h(sb + off, Bg + (size_t)r * K + k0 + ch * 8);
            }
        }
        asm volatile("cp.async.commit_group;");
    };

    load_stage(0);
    load_stage(1);

    int idx  = lane >> 3;
    int lrow = lane & 7;
    int a_mo = (idx & 1) * 8;
    int a_kc = idx >> 1;
    int b_no = (idx >> 1) * 8;
    int b_kc = idx & 1;

    for (int kt = 0; kt < KT; kt++) {
        asm volatile("cp.async.wait_group 1;");
        __syncthreads();
        load_stage(kt + 2);

        u32 sa = sbase + (u32)(kt % NSTAGE) * STAGE_BYTES;
        u32 sb = sa + ASTAGE_BYTES;

#pragma unroll
        for (int ks = 0; ks < 4; ks++) {
            u32 a[4][4];
#pragma unroll
            for (int mt = 0; mt < 4; mt++) {
                int r  = wm * 64 + mt * 16 + a_mo + lrow;
                int ch = ks * 2 + a_kc;
                ldsm4(a[mt][0], a[mt][1], a[mt][2], a[mt][3],
                      sa + (u32)(r * 8 + (ch ^ (r & 7))) * 16u);
            }
            u32 b[4][2];
#pragma unroll
            for (int nt2 = 0; nt2 < 2; nt2++) {
                int r  = wn * 32 + nt2 * 16 + b_no + lrow;
                int ch = ks * 2 + b_kc;
                u32 t0, t1, t2, t3;
                ldsm4(t0, t1, t2, t3, sb + (u32)(r * 8 + (ch ^ (r & 7))) * 16u);
                b[nt2 * 2][0] = t0; b[nt2 * 2][1] = t1;
                b[nt2 * 2 + 1][0] = t2; b[nt2 * 2 + 1][1] = t3;
            }
#pragma unroll
            for (int mt = 0; mt < 4; mt++)
#pragma unroll
                for (int nt = 0; nt < 4; nt++)
                    mma16816(c[mt][nt], a[mt], b[nt]);
        }
        __syncthreads();
    }

#pragma unroll
    for (int mt = 0; mt < 4; mt++) {
#pragma unroll
        for (int nt = 0; nt < 4; nt++) {
            int row = m0 + wm * 64 + mt * 16 + (lane >> 2);
            int col = n0 + wn * 32 + nt * 8 + (lane & 3) * 2;
            float2 bv = *(const float2*)(bias + col);
            float v0 = c[mt][nt][0] + bv.x;
            float v1 = c[mt][nt][1] + bv.y;
            float v2 = c[mt][nt][2] + bv.x;
            float v3 = c[mt][nt][3] + bv.y;
            if (mode == 2) {
                v0 = fmaxf(v0, 0.f); v1 = fmaxf(v1, 0.f);
                v2 = fmaxf(v2, 0.f); v3 = fmaxf(v3, 0.f);
            }
            if (mode) {
                *(__half2*)(C16 + (size_t)row * Nn + col) = __floats2half2_rn(v0, v1);
                *(__half2*)(C16 + (size_t)(row + 8) * Nn + col) = __floats2half2_rn(v2, v3);
            } else {
                float2 o0 = {v0, v1};
                float2 o1 = {v2, v3};
                *(float2*)(C32 + (size_t)row * Nn + col) = o0;
                *(float2*)(C32 + (size_t)(row + 8) * Nn + col) = o1;
            }
        }
    }
}

// ---------------- flash attention via mma + f16x2 exp ------------------------
// block = (window, head); 128 threads = 4 warps; each warp owns 32 query rows
#define QK_STRB 80    // 40 halfs row stride (bytes)
#define VT_STRB 272   // 136 halfs row stride (bytes)
__device__ __forceinline__ u32 h2ex2(u32 x) {
    u32 r;
    asm volatile("ex2.approx.f16x2 %0, %1;" : "=r"(r) : "r"(x));
    return r;
}
__device__ __forceinline__ u32 packh2(float a, float b) {
    __half2 h = __floats2half2_rn(a, b);
    return *(u32*)&h;
}

__global__ __launch_bounds__(128) void attn_mma_kernel(const __half* __restrict__ qkv,
                                                       __half* __restrict__ att16) {
    __shared__ __align__(16) __half Qs[128 * 40];
    __shared__ __align__(16) __half Ks[128 * 40];
    __shared__ __align__(16) __half Vt[32 * 136];

    int w = blockIdx.x;
    int h = blockIdx.y;
    int p = threadIdx.x;
    int lane = p & 31;
    int warp = p >> 5;

    // load q,k rows; transpose v
    {
        const __half* base = qkv + ((size_t)w * WS + p) * 768 + h * 32;
        const uint4* q4 = (const uint4*)base;
        const uint4* k4 = (const uint4*)(base + 256);
        const uint4* v4 = (const uint4*)(base + 512);
        uint4* qd = (uint4*)(Qs + p * 40);
        uint4* kd = (uint4*)(Ks + p * 40);
#pragma unroll
        for (int c = 0; c < 4; c++) { qd[c] = q4[c]; kd[c] = k4[c]; }
        union { uint4 u[4]; __half hh[32]; } vv;
#pragma unroll
        for (int c = 0; c < 4; c++) vv.u[c] = v4[c];
#pragma unroll
        for (int d = 0; d < 32; d++) Vt[d * 136 + p] = vv.hh[d];
    }
    __syncthreads();

    u32 qsb = (u32)__cvta_generic_to_shared(Qs);
    u32 ksb = (u32)__cvta_generic_to_shared(Ks);
    u32 vtb = (u32)__cvta_generic_to_shared(Vt);

    int idx  = lane >> 3;
    int lrow = lane & 7;
    int a_mo = (idx & 1) * 8;
    int a_kc = idx >> 1;
    int b_no = (idx >> 1) * 8;
    int b_kc = idx & 1;
    int m_base = warp * 32;

    const float scale = 0.2550540263f;  // log2(e)/sqrt(32)

    float mrow[2][2], lrow_s[2][2];
    float o[2][4][4];
#pragma unroll
    for (int t = 0; t < 2; t++)
#pragma unroll
        for (int rh = 0; rh < 2; rh++) { mrow[t][rh] = -1e30f; lrow_s[t][rh] = 0.f; }
#pragma unroll
    for (int t = 0; t < 2; t++)
#pragma unroll
        for (int n = 0; n < 4; n++)
#pragma unroll
            for (int k = 0; k < 4; k++) o[t][n][k] = 0.f;

#pragma unroll
    for (int chunk = 0; chunk < 2; chunk++) {
        int n0c = chunk * 64;

        // ---- S = Q K^T over this 64-key chunk ----
        float s[2][8][4];
#pragma unroll
        for (int t = 0; t < 2; t++)
#pragma unroll
            for (int n = 0; n < 8; n++)
#pragma unroll
                for (int k = 0; k < 4; k++) s[t][n][k] = 0.f;

#pragma unroll
        for (int ks = 0; ks < 2; ks++) {
            u32 a[2][4];
#pragma unroll
            for (int t = 0; t < 2; t++) {
                int r  = m_base + t * 16 + a_mo + lrow;
                int ch = ks * 2 + a_kc;
                ldsm4(a[t][0], a[t][1], a[t][2], a[t][3],
                      qsb + (u32)(r * QK_STRB + ch * 16));
            }
            u32 b[8][2];
#pragma unroll
            for (int np = 0; np < 4; np++) {
                int r  = n0c + np * 16 + b_no + lrow;
                int ch = ks * 2 + b_kc;
                u32 t0, t1, t2, t3;
                ldsm4(t0, t1, t2, t3, ksb + (u32)(r * QK_STRB + ch * 16));
                b[np * 2][0] = t0; b[np * 2][1] = t1;
                b[np * 2 + 1][0] = t2; b[np * 2 + 1][1] = t3;
            }
#pragma unroll
            for (int t = 0; t < 2; t++)
#pragma unroll
                for (int n = 0; n < 8; n++)
                    mma16816(s[t][n], a[t], b[n]);
        }

        // ---- softmax (log2 domain), P in fp16 fragments ----
        u32 pf_lo[2][8], pf_hi[2][8];
#pragma unroll
        for (int t = 0; t < 2; t++) {
            // row-half 0 (row r): elements s[t][n][0..1]; row-half 1: s[t][n][2..3]
#pragma unroll
            for (int rh = 0; rh < 2; rh++) {
                float cm = -1e30f;
#pragma unroll
                for (int n = 0; n < 8; n++) {
                    float v0 = s[t][n][rh * 2]     * scale;
                    float v1 = s[t][n][rh * 2 + 1] * scale;
                    cm = fmaxf(cm, fmaxf(v0, v1));
                }
                cm = fmaxf(cm, __shfl_xor_sync(0xffffffffu, cm, 1));
                cm = fmaxf(cm, __shfl_xor_sync(0xffffffffu, cm, 2));
                float mnew = fmaxf(mrow[t][rh], cm);
                float corr = exp2f(mrow[t][rh] - mnew);
                mrow[t][rh] = mnew;
                lrow_s[t][rh] *= corr;
#pragma unroll
                for (int n = 0; n < 4; n++) {
                    o[t][n][rh * 2]     *= corr;
                    o[t][n][rh * 2 + 1] *= corr;
                }
                float lsum = 0.f;
#pragma unroll
                for (int n = 0; n < 8; n++) {
                    float v0 = s[t][n][rh * 2]     * scale - mnew;
                    float v1 = s[t][n][rh * 2 + 1] * scale - mnew;
                    u32 pp = h2ex2(packh2(v0, v1));
                    if (rh == 0) pf_lo[t][n] = pp; else pf_hi[t][n] = pp;
                    __half2 ph = *(__half2*)&pp;
                    float2 pfv = __half22float2(ph);
                    lsum += pfv.x + pfv.y;
                }
                lrow_s[t][rh] += lsum;
            }
        }

        // ---- O += P V  (k = 64 keys of this chunk) ----
#pragma unroll
        for (int ks2 = 0; ks2 < 4; ks2++) {
            u32 b[4][2];
#pragma unroll
            for (int np = 0; np < 2; np++) {
                int r = np * 16 + b_no + lrow;
                int kh = n0c + ks2 * 16 + b_kc * 8;
                u32 t0, t1, t2, t3;
                ldsm4(t0, t1, t2, t3, vtb + (u32)(r * VT_STRB + kh * 2));
                b[np * 2][0] = t0; b[np * 2][1] = t1;
                b[np * 2 + 1][0] = t2; b[np * 2 + 1][1] = t3;
            }
#pragma unroll
            for (int t = 0; t < 2; t++) {
                u32 a[4];
                a[0] = pf_lo[t][ks2 * 2];
                a[1] = pf_hi[t][ks2 * 2];
                a[2] = pf_lo[t][ks2 * 2 + 1];
                a[3] = pf_hi[t][ks2 * 2 + 1];
#pragma unroll
                for (int n = 0; n < 4; n++)
                    mma16816(o[t][n], a, b[n]);
            }
        }
    }

    // ---- finalize: quad-reduce l, normalize, store fp16 ----
#pragma unroll
    for (int t = 0; t < 2; t++) {
#pragma unroll
        for (int rh = 0; rh < 2; rh++) {
            float lr = lrow_s[t][rh];
            lr += __shfl_xor_sync(0xffffffffu, lr, 1);
            lr += __shfl_xor_sync(0xffffffffu, lr, 2);
            float inv = 1.f / lr;
            int row = w * WS + m_base + t * 16 + (lane >> 2) + rh * 8;
            __half* outp = att16 + (size_t)row * 256 + h * 32 + (lane & 3) * 2;
#pragma unroll
            for (int n = 0; n < 4; n++) {
                *(__half2*)(outp + n * 8) =
                    __floats2half2_rn(o[t][n][rh * 2] * inv, o[t][n][rh * 2 + 1] * inv);
            }
        }
    }
}

// ---------------- residual add + LayerNorm ------------------------------------
__global__ void add_ln_kernel(const float* __restrict__ resid,
                              const float* __restrict__ delta,
                              const float* __restrict__ gamma,
                              const float* __restrict__ beta,
                              float* __restrict__ out,
                              __half* __restrict__ out16) {
    int row = blockIdx.x;
    int t = threadIdx.x;
    size_t idx = (size_t)row * 256 + t;
    float v = resid[idx] + delta[idx];

    __shared__ float red[8];
    float s = v;
#pragma unroll
    for (int o = 16; o > 0; o >>= 1) s += __shfl_xor_sync(0xffffffffu, s, o);
    if ((t & 31) == 0) red[t >> 5] = s;
    __syncthreads();
    if (t < 32) {
        float xr = (t < 8) ? red[t] : 0.f;
#pragma unroll
        for (int o = 4; o > 0; o >>= 1) xr += __shfl_xor_sync(0xffffffffu, xr, o);
        if (t == 0) red[0] = xr;
    }
    __syncthreads();
    float mean = red[0] * (1.f / 256.f);
    __syncthreads();

    float d = v - mean;
    float s2 = d * d;
#pragma unroll
    for (int o = 16; o > 0; o >>= 1) s2 += __shfl_xor_sync(0xffffffffu, s2, o);
    if ((t & 31) == 0) red[t >> 5] = s2;
    __syncthreads();
    if (t < 32) {
        float xr = (t < 8) ? red[t] : 0.f;
#pragma unroll
        for (int o = 4; o > 0; o >>= 1) xr += __shfl_xor_sync(0xffffffffu, xr, o);
        if (t == 0) red[0] = xr;
    }
    __syncthreads();
    float var = red[0] * (1.f / 256.f);
    float r = d * rsqrtf(var + 1e-5f) * gamma[t] + beta[t];
    out[idx] = r;
    out16[idx] = __float2half_rn(r);
}

// ---------------- launch ------------------------------------------------------
extern "C" void kernel_launch(void* const* d_in, const int* in_sizes, int n_in,
                              void* d_out, int out_size) {
    const int*   coords = (const int*)d_in[0];
    const float* feat   = (const float*)d_in[1];
    const float* pex    = (const float*)d_in[2];
    const float* pey    = (const float*)d_in[3];
    const float* pez    = (const float*)d_in[4];
    const float* pes    = (const float*)d_in[5];
    const float* Wqkv   = (const float*)d_in[6];
    const float* bqkv   = (const float*)d_in[7];
    const float* Wo     = (const float*)d_in[8];
    const float* bo     = (const float*)d_in[9];
    const float* W1     = (const float*)d_in[10];
    const float* b1     = (const float*)d_in[11];
    const float* W2     = (const float*)d_in[12];
    const float* b2     = (const float*)d_in[13];
    const float* g1     = (const float*)d_in[14];
    const float* be1    = (const float*)d_in[15];
    const float* g2     = (const float*)d_in[16];
    const float* be2    = (const float*)d_in[17];

    u64 *ka, *kb;
    float *xp, *tmpp;
    __half *qkv16p, *x16p, *att16p, *ff16p, *w16p;
    cudaGetSymbolAddress((void**)&ka,     g_keysA);
    cudaGetSymbolAddress((void**)&kb,     g_keysB);
    cudaGetSymbolAddress((void**)&xp,     g_x);
    cudaGetSymbolAddress((void**)&tmpp,   g_tmp);
    cudaGetSymbolAddress((void**)&qkv16p, g_qkv16);
    cudaGetSymbolAddress((void**)&x16p,   g_x16);
    cudaGetSymbolAddress((void**)&att16p, g_att16);
    cudaGetSymbolAddress((void**)&ff16p,  g_ff16);
    cudaGetSymbolAddress((void**)&w16p,   g_w16);

    static int attr_done = 0;
    if (!attr_done) {
        cudaFuncSetAttribute(gemm_f16_kernel,
                             cudaFuncAttributeMaxDynamicSharedMemorySize, GEMM_SMEM);
        attr_done = 1;
    }

    // 0) weights -> fp16
    cvt_f16_kernel<<<(786432  + 255) / 256, 256>>>(Wqkv, w16p + WOFF_QKV, 786432);
    cvt_f16_kernel<<<(262144  + 255) / 256, 256>>>(Wo,   w16p + WOFF_O,   262144);
    cvt_f16_kernel<<<(2097152 + 255) / 256, 256>>>(W1,   w16p + WOFF_1,   2097152);
    cvt_f16_kernel<<<(2097152 + 255) / 256, 256>>>(W2,   w16p + WOFF_2,   2097152);

    // 1) sort
    build_keys_kernel<<<256, 256>>>(coords, ka);
    int shifts[3] = {16, 24, 32};
    u64* src = ka;
    u64* dst = kb;
    for (int p = 0; p < 3; p++) {
        radix_hist_kernel<<<256, 256>>>(src, shifts[p]);
        radix_scan_kernel<<<1, 256>>>();
        radix_scatter_kernel<<<256, 256>>>(src, dst, shifts[p]);
        u64* t = src; src = dst; dst = t;
    }

    // 2) gather + PE
    gather_pe_kernel<<<N_PTS, 256>>>(src, coords, feat, pex, pey, pez, pes, xp, x16p);

    // 3) layers
    for (int l = 0; l < NLAYER; l++) {
        const __half* wqkv = w16p + WOFF_QKV + (size_t)l * 768 * 256;
        const float*  bq   = bqkv + (size_t)l * 768;
        const __half* wo   = w16p + WOFF_O + (size_t)l * 256 * 256;
        const float*  bo_l = bo   + (size_t)l * 256;
        const __half* w1   = w16p + WOFF_1 + (size_t)l * 2048 * 256;
        const float*  b1_l = b1   + (size_t)l * 2048;
        const __half* w2   = w16p + WOFF_2 + (size_t)l * 256 * 2048;
        const float*  b2_l = b2   + (size_t)l * 256;

        // qkv (fp16 out)
        gemm_f16_kernel<<<dim3(768 / GBN, N_PTS / GBM), 256, GEMM_SMEM>>>(
            x16p, wqkv, bq, nullptr, qkv16p, 768, 256, 1);

        attn_mma_kernel<<<dim3(N_PTS / WS, NH), 128>>>(qkv16p, att16p);

        gemm_f16_kernel<<<dim3(256 / GBN, N_PTS / GBM), 256, GEMM_SMEM>>>(
            att16p, wo, bo_l, tmpp, nullptr, 256, 256, 0);

        add_ln_kernel<<<N_PTS, 256>>>(xp, tmpp, g1 + l * 256, be1 + l * 256, xp, x16p);

        gemm_f16_kernel<<<dim3(2048 / GBN, N_PTS / GBM), 256, GEMM_SMEM>>>(
            x16p, w1, b1_l, nullptr, ff16p, 2048, 256, 2);

        gemm_f16_kernel<<<dim3(256 / GBN, N_PTS / GBM), 256, GEMM_SMEM>>>(
            ff16p, w2, b2_l, tmpp, nullptr, 256, 2048, 0);

        add_ln_kernel<<<N_PTS, 256>>>(xp, tmpp, g2 + l * 256, be2 + l * 256, xp, x16p);
    }

    // 4) output
    cudaMemcpyAsync(d_out, xp, (size_t)N_PTS * D_MODEL * sizeof(float),
                    cudaMemcpyDeviceToDevice);
}